// round 11
// baseline (speedup 1.0000x reference)
#include <cuda_runtime.h>
#include <math.h>

#define B_  2
#define S_  2048
#define HID 1024
#define NH  16
#define NKV 4
#define HD  64
#define MROWS (B_*S_)   // 4096

// Scratch (no cudaMalloc allowed)
__device__ float g_Q[MROWS * HID];        // [B,S,NH,HD]
__device__ float g_K[MROWS * NKV * HD];   // [B,S,NKV,HD]
__device__ float g_V[MROWS * NKV * HD];
__device__ float g_A[MROWS * HID];        // attention output [B,S,NH,HD]

__device__ __forceinline__ unsigned f2tf32(float x) {
    unsigned r;
    asm("cvt.rna.tf32.f32 %0, %1;" : "=r"(r) : "f"(x));
    return r;
}

// ---------------------------------------------------------------------------
// tf32 tensor-core GEMM (mma.sync m16n8k8): C[M,N] = A[M,K] @ W[N,K]^T.
// R8 structure (double-buffered ping-pong smem, register-staged prefetch,
// one sync per K-step, dual-output mode for the K+V launch) with a NEW
// k-pair interleaved smem layout:
//   within each 8-col k-group, column order is [k0,k0+4,k0+1,k0+5,k0+2,...]
//   so each fragment (tig, tig+4) pair is ONE LDS.64. Row stride 40 makes
//   all LDS.64 fragment loads conflict-free per half-warp, and the loader
//   writes with conflict-free STS.128.
// ---------------------------------------------------------------------------
#define TST 40
#define GEMM_SMEM (2 * 2 * 128 * TST * 4)   // 81920 B dynamic

__global__ __launch_bounds__(256) void sgemm_tf32(
    const float* __restrict__ A,
    const float* __restrict__ W1, float* __restrict__ C1, int nx1, int rope1,
    const float* __restrict__ W2, float* __restrict__ C2, int rope2,
    int M, int N, int K,
    const float* __restrict__ cosT, const float* __restrict__ sinT)
{
    extern __shared__ unsigned gsm[];
    unsigned* As = gsm;                 // [2][128*TST]
    unsigned* Bs = gsm + 2*128*TST;     // [2][128*TST]

    int bx = blockIdx.x;
    const float* W; float* C; int rope;
    if (bx < nx1) { W = W1; C = C1; rope = rope1; }
    else          { W = W2; C = C2; rope = rope2; bx -= nx1; }

    const int t    = threadIdx.x;
    const int wid  = t >> 5;
    const int lane = t & 31;
    const int grp  = lane >> 2;
    const int tig  = lane & 3;
    const int wm   = (wid >> 1) * 32;   // 4 row-warps
    const int wn   = (wid & 1) * 64;    // 2 col-warps

    // loader: idx = t + i*256 -> row r = idx>>3, segment s = idx&7.
    // gmem float2 cols g0 = 8*(s>>1) + 2*(s&1) and g0+4; smem word off = r*40 + 4*s.
    const int lr  = t >> 3;             // row base (0..31), +32 per i
    const int ls  = t & 7;              // segment
    const int lg0 = 8*(ls >> 1) + 2*(ls & 1);
    const int lso = 4*ls;

    const float* Ab = A + (size_t)(blockIdx.y * 128) * K;
    const float* Wb = W + (size_t)(bx * 128) * K;

    float acc[2][8][4];
#pragma unroll
    for (int mf = 0; mf < 2; mf++)
#pragma unroll
        for (int nf = 0; nf < 8; nf++) {
            acc[mf][nf][0]=0.f; acc[mf][nf][1]=0.f;
            acc[mf][nf][2]=0.f; acc[mf][nf][3]=0.f;
        }

    // ---- preload tile k0=0 into buffer 0 (interleaved pairs, STS.128)
#pragma unroll
    for (int i = 0; i < 4; i++) {
        int r = lr + i*32;
        float2 u = *(const float2*)(Ab + (size_t)r * K + lg0);
        float2 v = *(const float2*)(Ab + (size_t)r * K + lg0 + 4);
        *(uint4*)&As[r*TST + lso] =
            make_uint4(f2tf32(u.x), f2tf32(v.x), f2tf32(u.y), f2tf32(v.y));
    }
#pragma unroll
    for (int i = 0; i < 4; i++) {
        int r = lr + i*32;
        float2 u = *(const float2*)(Wb + (size_t)r * K + lg0);
        float2 v = *(const float2*)(Wb + (size_t)r * K + lg0 + 4);
        *(uint4*)&Bs[r*TST + lso] =
            make_uint4(f2tf32(u.x), f2tf32(v.x), f2tf32(u.y), f2tf32(v.y));
    }
    __syncthreads();

    int buf = 0;
    for (int k0 = 0; k0 < K; k0 += 32) {
        const bool more = (k0 + 32 < K);
        const unsigned* Ac = As + buf*128*TST;
        const unsigned* Bc = Bs + buf*128*TST;
        unsigned* An = As + (buf^1)*128*TST;
        unsigned* Bn = Bs + (buf^1)*128*TST;

        // stage A for next tile
        float2 rau[4], rav[4];
        if (more) {
#pragma unroll
            for (int i = 0; i < 4; i++) {
                const float* p = Ab + (size_t)(lr + i*32) * K + k0 + 32 + lg0;
                rau[i] = *(const float2*)(p);
                rav[i] = *(const float2*)(p + 4);
            }
        }

        // MMAs k8 = 0,1
#pragma unroll
        for (int k8 = 0; k8 < 2; k8++) {
            const int kb = k8 * 8;
            unsigned af[2][4];
#pragma unroll
            for (int mf = 0; mf < 2; mf++) {
                int mrow = wm + mf*16 + grp;
                uint2 lo = *(const uint2*)&Ac[(mrow  )*TST + kb + 2*tig];
                uint2 hi = *(const uint2*)&Ac[(mrow+8)*TST + kb + 2*tig];
                af[mf][0] = lo.x; af[mf][1] = hi.x;
                af[mf][2] = lo.y; af[mf][3] = hi.y;
            }
#pragma unroll
            for (int nf = 0; nf < 8; nf++) {
                int n = wn + nf*8 + grp;
                uint2 bv = *(const uint2*)&Bc[n*TST + kb + 2*tig];
#pragma unroll
                for (int mf = 0; mf < 2; mf++) {
                    float* c0 = &acc[mf][nf][0];
                    asm volatile(
                        "mma.sync.aligned.m16n8k8.row.col.f32.tf32.tf32.f32 "
                        "{%0,%1,%2,%3}, {%4,%5,%6,%7}, {%8,%9}, {%0,%1,%2,%3};"
                        : "+f"(c0[0]), "+f"(c0[1]), "+f"(c0[2]), "+f"(c0[3])
                        : "r"(af[mf][0]), "r"(af[mf][1]), "r"(af[mf][2]), "r"(af[mf][3]),
                          "r"(bv.x), "r"(bv.y));
                }
            }
        }

        // store staged A into next buffer, stage B
        float2 rbu[4], rbv[4];
        if (more) {
#pragma unroll
            for (int i = 0; i < 4; i++) {
                int r = lr + i*32;
                *(uint4*)&An[r*TST + lso] =
                    make_uint4(f2tf32(rau[i].x), f2tf32(rav[i].x),
                               f2tf32(rau[i].y), f2tf32(rav[i].y));
            }
#pragma unroll
            for (int i = 0; i < 4; i++) {
                const float* p = Wb + (size_t)(lr + i*32) * K + k0 + 32 + lg0;
                rbu[i] = *(const float2*)(p);
                rbv[i] = *(const float2*)(p + 4);
            }
        }

        // MMAs k8 = 2,3
#pragma unroll
        for (int k8 = 2; k8 < 4; k8++) {
            const int kb = k8 * 8;
            unsigned af[2][4];
#pragma unroll
            for (int mf = 0; mf < 2; mf++) {
                int mrow = wm + mf*16 + grp;
                uint2 lo = *(const uint2*)&Ac[(mrow  )*TST + kb + 2*tig];
                uint2 hi = *(const uint2*)&Ac[(mrow+8)*TST + kb + 2*tig];
                af[mf][0] = lo.x; af[mf][1] = hi.x;
                af[mf][2] = lo.y; af[mf][3] = hi.y;
            }
#pragma unroll
            for (int nf = 0; nf < 8; nf++) {
                int n = wn + nf*8 + grp;
                uint2 bv = *(const uint2*)&Bc[n*TST + kb + 2*tig];
#pragma unroll
                for (int mf = 0; mf < 2; mf++) {
                    float* c0 = &acc[mf][nf][0];
                    asm volatile(
                        "mma.sync.aligned.m16n8k8.row.col.f32.tf32.tf32.f32 "
                        "{%0,%1,%2,%3}, {%4,%5,%6,%7}, {%8,%9}, {%0,%1,%2,%3};"
                        : "+f"(c0[0]), "+f"(c0[1]), "+f"(c0[2]), "+f"(c0[3])
                        : "r"(af[mf][0]), "r"(af[mf][1]), "r"(af[mf][2]), "r"(af[mf][3]),
                          "r"(bv.x), "r"(bv.y));
                }
            }
        }

        if (more) {
#pragma unroll
            for (int i = 0; i < 4; i++) {
                int r = lr + i*32;
                *(uint4*)&Bn[r*TST + lso] =
                    make_uint4(f2tf32(rbu[i].x), f2tf32(rbv[i].x),
                               f2tf32(rbu[i].y), f2tf32(rbv[i].y));
            }
            __syncthreads();
            buf ^= 1;
        }
    }

    // Optional fused RoPE: lo cols are nf<4 (i = nf*8+tig*2 < 32), hi = nf+4.
    if (rope) {
#pragma unroll
        for (int mf = 0; mf < 2; mf++) {
#pragma unroll
            for (int nf = 0; nf < 4; nf++) {
                const int i0 = nf*8 + tig*2;
#pragma unroll
                for (int hh = 0; hh < 2; hh++) {
                    int row = blockIdx.y*128 + wm + mf*16 + grp + hh*8;
                    int s   = row & (S_ - 1);
#pragma unroll
                    for (int j = 0; j < 2; j++) {
                        float c  = cosT[s*HD + i0 + j];
                        float sn = sinT[s*HD + i0 + j];
                        float L = acc[mf][nf  ][hh*2 + j];
                        float H = acc[mf][nf+4][hh*2 + j];
                        acc[mf][nf  ][hh*2 + j] = L*c - H*sn;
                        acc[mf][nf+4][hh*2 + j] = H*c + L*sn;
                    }
                }
            }
        }
    }

#pragma unroll
    for (int mf = 0; mf < 2; mf++) {
#pragma unroll
        for (int nf = 0; nf < 8; nf++) {
            float* c0 = &acc[mf][nf][0];
            int row = blockIdx.y*128 + wm + mf*16 + grp;
            int col = bx*128 + wn + nf*8 + tig*2;
            *(float2*)(C + (size_t)row*N + col)     = make_float2(c0[0], c0[1]);
            *(float2*)(C + (size_t)(row+8)*N + col) = make_float2(c0[2], c0[3]);
        }
    }
}

// ---------------------------------------------------------------------------
// Tensor-core causal flash attention v3 (tf32 mma.sync) -- exact R5/R8 code
// (measured 155.5us). 128 threads, BM=128, BN=64, Q in registers.
// ---------------------------------------------------------------------------
#define FST 68
#define FA_SMEM ((64*FST*2 + 128*FST) * 4)   // Ks + Vs + Ps = 69632 B

__global__ __launch_bounds__(128) void flash_attn_mma3(
    const float* __restrict__ Q, const float* __restrict__ K,
    const float* __restrict__ V, float* __restrict__ O)
{
    extern __shared__ unsigned fsm[];
    unsigned* Ks = fsm;              // [64][FST]
    unsigned* Vs = Ks + 64*FST;      // [64][FST]
    unsigned* Ps = Vs + 64*FST;      // [128][FST]

    const int h  = blockIdx.x;
    const int bm = (gridDim.y - 1) - blockIdx.y;   // heaviest blocks first
    const int b  = blockIdx.z;
    const int hk = h >> 2;                          // GQA
    const int t    = threadIdx.x;
    const int w    = t >> 5;
    const int lane = t & 31;
    const int grp  = lane >> 2;
    const int tig  = lane & 3;
    const int rb   = bm*128 + w*32;   // warp's first q row (global)

    // ---- Q fragments: 2 mf x 8 kb x 4 regs, scaled by 1/8, tf32
    unsigned qf[2][8][4];
#pragma unroll
    for (int mf = 0; mf < 2; mf++) {
        const float* q0 = Q + (((size_t)(b*S_ + rb + mf*16 + grp    )*NH + h) << 6);
        const float* q1 = Q + (((size_t)(b*S_ + rb + mf*16 + grp + 8)*NH + h) << 6);
#pragma unroll
        for (int kb = 0; kb < 8; kb++) {
            qf[mf][kb][0] = f2tf32(0.125f * q0[kb*8 + tig]);
            qf[mf][kb][1] = f2tf32(0.125f * q1[kb*8 + tig]);
            qf[mf][kb][2] = f2tf32(0.125f * q0[kb*8 + tig + 4]);
            qf[mf][kb][3] = f2tf32(0.125f * q1[kb*8 + tig + 4]);
        }
    }

    float oacc[2][8][4];
#pragma unroll
    for (int mf = 0; mf < 2; mf++)
#pragma unroll
        for (int nf = 0; nf < 8; nf++) {
            oacc[mf][nf][0]=0.f; oacc[mf][nf][1]=0.f;
            oacc[mf][nf][2]=0.f; oacc[mf][nf][3]=0.f;
        }
    float m[4]  = {-1e30f, -1e30f, -1e30f, -1e30f};
    float l[4]  = {0.f, 0.f, 0.f, 0.f};

    const int ntiles = 2*(bm + 1);
    for (int tile = 0; tile < ntiles; tile++) {
        __syncthreads();
        // ---- load K,V tile (64 keys x 64 dims), convert to tf32
#pragma unroll
        for (int i = 0; i < 8; i++) {
            int idx = t + i*128;
            int r   = idx >> 4;
            int c4  = (idx & 15) * 4;
            size_t gb = (((size_t)(b*S_ + tile*64 + r)*NKV + hk) << 6) + c4;
            float4 kv = *(const float4*)(K + gb);
            float4 vv = *(const float4*)(V + gb);
            unsigned* kd = &Ks[r*FST + c4];
            kd[0]=f2tf32(kv.x); kd[1]=f2tf32(kv.y); kd[2]=f2tf32(kv.z); kd[3]=f2tf32(kv.w);
            unsigned* vd = &Vs[r*FST + c4];
            vd[0]=f2tf32(vv.x); vd[1]=f2tf32(vv.y); vd[2]=f2tf32(vv.z); vd[3]=f2tf32(vv.w);
        }
        __syncthreads();

        // ---- S = (Q/8) K^T : per warp 32x64
        float sacc[2][8][4];
#pragma unroll
        for (int mf = 0; mf < 2; mf++)
#pragma unroll
            for (int nf = 0; nf < 8; nf++) {
                sacc[mf][nf][0]=0.f; sacc[mf][nf][1]=0.f;
                sacc[mf][nf][2]=0.f; sacc[mf][nf][3]=0.f;
            }
#pragma unroll
        for (int kb = 0; kb < 8; kb++) {
#pragma unroll
            for (int nf = 0; nf < 8; nf++) {
                unsigned b0 = Ks[(nf*8+grp)*FST + kb*8 + tig];
                unsigned b1 = Ks[(nf*8+grp)*FST + kb*8 + tig + 4];
#pragma unroll
                for (int mf = 0; mf < 2; mf++) {
                    float* c0 = &sacc[mf][nf][0];
                    asm volatile(
                        "mma.sync.aligned.m16n8k8.row.col.f32.tf32.tf32.f32 "
                        "{%0,%1,%2,%3}, {%4,%5,%6,%7}, {%8,%9}, {%0,%1,%2,%3};"
                        : "+f"(c0[0]), "+f"(c0[1]), "+f"(c0[2]), "+f"(c0[3])
                        : "r"(qf[mf][kb][0]), "r"(qf[mf][kb][1]),
                          "r"(qf[mf][kb][2]), "r"(qf[mf][kb][3]),
                          "r"(b0), "r"(b1));
                }
            }
        }

        // ---- online softmax on fragment layout
        const bool diag = (tile >= 2*bm);
        const int colb = tile*64;
#pragma unroll
        for (int mf = 0; mf < 2; mf++) {
            const int r0 = rb + mf*16 + grp;
            const int r1 = r0 + 8;
            float mt0 = -1e30f, mt1 = -1e30f;
#pragma unroll
            for (int nf = 0; nf < 8; nf++) {
                const int c0i = colb + nf*8 + tig*2;
                if (diag) {
                    if (c0i     > r0) sacc[mf][nf][0] = -1e30f;
                    if (c0i + 1 > r0) sacc[mf][nf][1] = -1e30f;
                    if (c0i     > r1) sacc[mf][nf][2] = -1e30f;
                    if (c0i + 1 > r1) sacc[mf][nf][3] = -1e30f;
                }
                mt0 = fmaxf(mt0, fmaxf(sacc[mf][nf][0], sacc[mf][nf][1]));
                mt1 = fmaxf(mt1, fmaxf(sacc[mf][nf][2], sacc[mf][nf][3]));
            }
            mt0 = fmaxf(mt0, __shfl_xor_sync(0xffffffffu, mt0, 1));
            mt0 = fmaxf(mt0, __shfl_xor_sync(0xffffffffu, mt0, 2));
            mt1 = fmaxf(mt1, __shfl_xor_sync(0xffffffffu, mt1, 1));
            mt1 = fmaxf(mt1, __shfl_xor_sync(0xffffffffu, mt1, 2));

            const float mn0 = fmaxf(m[mf*2  ], mt0);
            const float mn1 = fmaxf(m[mf*2+1], mt1);
            const float cr0 = __expf(m[mf*2  ] - mn0);
            const float cr1 = __expf(m[mf*2+1] - mn1);
            float ps0 = 0.f, ps1 = 0.f;

            unsigned* P0 = &Ps[(w*32 + mf*16 + grp)*FST + tig*2];
            unsigned* P1 = P0 + 8*FST;
#pragma unroll
            for (int nf = 0; nf < 8; nf++) {
                float p00 = __expf(sacc[mf][nf][0] - mn0);
                float p01 = __expf(sacc[mf][nf][1] - mn0);
                float p10 = __expf(sacc[mf][nf][2] - mn1);
                float p11 = __expf(sacc[mf][nf][3] - mn1);
                ps0 += p00 + p01;
                ps1 += p10 + p11;
                *(uint2*)(P0 + nf*8) = make_uint2(f2tf32(p00), f2tf32(p01));
                *(uint2*)(P1 + nf*8) = make_uint2(f2tf32(p10), f2tf32(p11));
            }
            ps0 += __shfl_xor_sync(0xffffffffu, ps0, 1);
            ps0 += __shfl_xor_sync(0xffffffffu, ps0, 2);
            ps1 += __shfl_xor_sync(0xffffffffu, ps1, 1);
            ps1 += __shfl_xor_sync(0xffffffffu, ps1, 2);
            l[mf*2  ] = l[mf*2  ]*cr0 + ps0;  m[mf*2  ] = mn0;
            l[mf*2+1] = l[mf*2+1]*cr1 + ps1;  m[mf*2+1] = mn1;
#pragma unroll
            for (int nf = 0; nf < 8; nf++) {
                oacc[mf][nf][0] *= cr0; oacc[mf][nf][1] *= cr0;
                oacc[mf][nf][2] *= cr1; oacc[mf][nf][3] *= cr1;
            }
        }
        __syncwarp();   // Ps region is warp-private

        // ---- O += P V
#pragma unroll
        for (int kb = 0; kb < 8; kb++) {
            unsigned a[2][4];
#pragma unroll
            for (int mf = 0; mf < 2; mf++) {
                const int pr = w*32 + mf*16 + grp;
                a[mf][0] = Ps[(pr    )*FST + kb*8 + tig];
                a[mf][1] = Ps[(pr + 8)*FST + kb*8 + tig];
                a[mf][2] = Ps[(pr    )*FST + kb*8 + tig + 4];
                a[mf][3] = Ps[(pr + 8)*FST + kb*8 + tig + 4];
            }
#pragma unroll
            for (int nf = 0; nf < 8; nf++) {
                unsigned b0 = Vs[(kb*8 + tig    )*FST + nf*8 + grp];
                unsigned b1 = Vs[(kb*8 + tig + 4)*FST + nf*8 + grp];
#pragma unroll
                for (int mf = 0; mf < 2; mf++) {
                    float* c0 = &oacc[mf][nf][0];
                    asm volatile(
                        "mma.sync.aligned.m16n8k8.row.col.f32.tf32.tf32.f32 "
                        "{%0,%1,%2,%3}, {%4,%5,%6,%7}, {%8,%9}, {%0,%1,%2,%3};"
                        : "+f"(c0[0]), "+f"(c0[1]), "+f"(c0[2]), "+f"(c0[3])
                        : "r"(a[mf][0]), "r"(a[mf][1]), "r"(a[mf][2]), "r"(a[mf][3]),
                          "r"(b0), "r"(b1));
                }
            }
        }
    }

    // ---- epilogue: O / l
#pragma unroll
    for (int mf = 0; mf < 2; mf++) {
        const float inv0 = 1.f / l[mf*2];
        const float inv1 = 1.f / l[mf*2+1];
        float* o0 = O + (((size_t)(b*S_ + rb + mf*16 + grp    )*NH + h) << 6) + tig*2;
        float* o1 = O + (((size_t)(b*S_ + rb + mf*16 + grp + 8)*NH + h) << 6) + tig*2;
#pragma unroll
        for (int nf = 0; nf < 8; nf++) {
            *(float2*)(o0 + nf*8) = make_float2(oacc[mf][nf][0]*inv0, oacc[mf][nf][1]*inv0);
            *(float2*)(o1 + nf*8) = make_float2(oacc[mf][nf][2]*inv1, oacc[mf][nf][3]*inv1);
        }
    }
}

// ---------------------------------------------------------------------------
extern "C" void kernel_launch(void* const* d_in, const int* in_sizes, int n_in,
                              void* d_out, int out_size)
{
    const float* x    = (const float*)d_in[0];
    const float* cosT = (const float*)d_in[1];
    const float* sinT = (const float*)d_in[2];
    const float* wq   = (const float*)d_in[3];
    const float* wk   = (const float*)d_in[4];
    const float* wv   = (const float*)d_in[5];
    const float* wo   = (const float*)d_in[6];
    float* out = (float*)d_out;

    float *Q, *K, *V, *Aat;
    cudaGetSymbolAddress((void**)&Q,   g_Q);
    cudaGetSymbolAddress((void**)&K,   g_K);
    cudaGetSymbolAddress((void**)&V,   g_V);
    cudaGetSymbolAddress((void**)&Aat, g_A);

    static bool attr_set = false;
    if (!attr_set) {
        cudaFuncSetAttribute(sgemm_tf32, cudaFuncAttributeMaxDynamicSharedMemorySize, GEMM_SMEM);
        cudaFuncSetAttribute(flash_attn_mma3, cudaFuncAttributeMaxDynamicSharedMemorySize, FA_SMEM);
        attr_set = true;
    }

    // Q projection (rope fused) -- 256 CTAs = one wave at 2 CTA/SM
    sgemm_tf32<<<dim3(HID/128, MROWS/128), 256, GEMM_SMEM>>>(
        x, wq, Q, HID/128, 1, nullptr, nullptr, 0,
        MROWS, HID, HID, cosT, sinT);

    // K (rope) + V projections merged into one launch -- 128 CTAs, one wave
    sgemm_tf32<<<dim3(2*(NKV*HD)/128, MROWS/128), 256, GEMM_SMEM>>>(
        x, wk, K, (NKV*HD)/128, 1, wv, V, 0,
        MROWS, NKV*HD, HID, cosT, sinT);

    // Tensor-core causal GQA flash attention
    flash_attn_mma3<<<dim3(NH, S_/128, B_), 128, FA_SMEM>>>(Q, K, V, Aat);

    // Output projection
    sgemm_tf32<<<dim3(HID/128, MROWS/128), 256, GEMM_SMEM>>>(
        Aat, wo, out, HID/128, 0, nullptr, nullptr, 0,
        MROWS, HID, HID, cosT, sinT);
}

// round 12
// speedup vs baseline: 1.2915x; 1.2915x over previous
#include <cuda_runtime.h>
#include <math.h>

#define B_  2
#define S_  2048
#define HID 1024
#define NH  16
#define NKV 4
#define HD  64
#define MROWS (B_*S_)   // 4096

// Scratch (no cudaMalloc allowed)
__device__ float g_Q[MROWS * HID];        // [B,S,NH,HD]
__device__ float g_K[MROWS * NKV * HD];   // [B,S,NKV,HD]
__device__ float g_V[MROWS * NKV * HD];
__device__ float g_A[MROWS * HID];        // attention output (tf32-rounded)
// tf32 (rna) pre-converted inputs
__device__ unsigned g_X [MROWS * HID];
__device__ unsigned g_Wq[HID * HID];
__device__ unsigned g_Wk[NKV * HD * HID];
__device__ unsigned g_Wv[NKV * HD * HID];
__device__ unsigned g_Wo[HID * HID];

__device__ __forceinline__ unsigned f2tf32(float x) {
    unsigned r;
    asm("cvt.rna.tf32.f32 %0, %1;" : "=r"(r) : "f"(x));
    return r;
}

__device__ __forceinline__ unsigned smem_u32(const void* p) {
    unsigned a;
    asm("{ .reg .u64 t; cvta.to.shared.u64 t, %1; cvt.u32.u64 %0, t; }"
        : "=r"(a) : "l"(p));
    return a;
}

// ---------------------------------------------------------------------------
// One-shot tf32 (rna) conversion of x and the four weight matrices.
// Segments (in 1024-float blocks): x 4096 | wq 1024 | wk 256 | wv 256 | wo 1024.
// ---------------------------------------------------------------------------
__global__ void conv_tf32(const float* __restrict__ x,  const float* __restrict__ wq,
                          const float* __restrict__ wk, const float* __restrict__ wv,
                          const float* __restrict__ wo,
                          unsigned* __restrict__ X,  unsigned* __restrict__ Wq,
                          unsigned* __restrict__ Wk, unsigned* __restrict__ Wv,
                          unsigned* __restrict__ Wo)
{
    int blk = blockIdx.x;
    const float* src; unsigned* dst; int base;
    if      (blk < 4096) { src = x;  dst = X;  base = blk; }
    else if (blk < 5120) { src = wq; dst = Wq; base = blk - 4096; }
    else if (blk < 5376) { src = wk; dst = Wk; base = blk - 5120; }
    else if (blk < 5632) { src = wv; dst = Wv; base = blk - 5376; }
    else                 { src = wo; dst = Wo; base = blk - 5632; }
    int idx = base * 1024 + threadIdx.x * 4;
    float4 v = *(const float4*)(src + idx);
    *(uint4*)(dst + idx) = make_uint4(f2tf32(v.x), f2tf32(v.y), f2tf32(v.z), f2tf32(v.w));
}
#define CONV_BLOCKS (4096 + 1024 + 256 + 256 + 1024)

// ---------------------------------------------------------------------------
// tf32 tensor-core GEMM (mma.sync m16n8k8): C[M,N] = A[M,K] @ W[N,K]^T.
// Inputs are PRE-CONVERTED tf32. Loader = pure cp.async (zero staging regs,
// zero in-loop converts). Double-buffered, one sync per K-step, R8 MMA loop
// (TST=36, scalar LDS, measured). Dual-output mode merges K+V projections.
// ---------------------------------------------------------------------------
#define TST 36
#define GEMM_SMEM (2 * 2 * 128 * TST * 4)   // 73728 B dynamic

__global__ __launch_bounds__(256) void sgemm_tf32(
    const unsigned* __restrict__ A,
    const unsigned* __restrict__ W1, float* __restrict__ C1, int nx1, int rope1,
    const unsigned* __restrict__ W2, float* __restrict__ C2, int rope2,
    int M, int N, int K,
    const float* __restrict__ cosT, const float* __restrict__ sinT)
{
    extern __shared__ unsigned gsm[];
    unsigned* As = gsm;                 // [2][128*TST]
    unsigned* Bs = gsm + 2*128*TST;     // [2][128*TST]

    int bx = blockIdx.x;
    const unsigned* W; float* C; int rope;
    if (bx < nx1) { W = W1; C = C1; rope = rope1; }
    else          { W = W2; C = C2; rope = rope2; bx -= nx1; }

    const int t    = threadIdx.x;
    const int wid  = t >> 5;
    const int lane = t & 31;
    const int grp  = lane >> 2;
    const int tig  = lane & 3;
    const int wm   = (wid >> 1) * 32;   // 4 row-warps
    const int wn   = (wid & 1) * 64;    // 2 col-warps

    const int lr  = t >> 3;             // loader row base (0..31), +32 per chunk
    const int lc4 = (t & 7) * 4;        // loader col (0..28)

    const unsigned* Ab = A + (size_t)(blockIdx.y * 128) * K;
    const unsigned* Wb = W + (size_t)(bx * 128) * K;

    const unsigned sa = smem_u32(As);
    const unsigned sb = smem_u32(Bs);

    float acc[2][8][4];
#pragma unroll
    for (int mf = 0; mf < 2; mf++)
#pragma unroll
        for (int nf = 0; nf < 8; nf++) {
            acc[mf][nf][0]=0.f; acc[mf][nf][1]=0.f;
            acc[mf][nf][2]=0.f; acc[mf][nf][3]=0.f;
        }

    // ---- preload tile k0=0 into buffer 0 (cp.async)
#pragma unroll
    for (int i = 0; i < 4; i++) {
        int r = lr + i*32;
        unsigned da = sa + (unsigned)(r*TST + lc4) * 4u;
        unsigned db = sb + (unsigned)(r*TST + lc4) * 4u;
        asm volatile("cp.async.cg.shared.global [%0], [%1], 16;"
                     :: "r"(da), "l"(Ab + (size_t)r * K + lc4) : "memory");
        asm volatile("cp.async.cg.shared.global [%0], [%1], 16;"
                     :: "r"(db), "l"(Wb + (size_t)r * K + lc4) : "memory");
    }
    asm volatile("cp.async.commit_group;" ::: "memory");

    int buf = 0;
    for (int k0 = 0; k0 < K; k0 += 32) {
        const bool more = (k0 + 32 < K);
        asm volatile("cp.async.wait_group 0;" ::: "memory");   // tile k0 ready
        __syncthreads();   // visible to all; all threads done with prev tile's MMAs

        if (more) {
            const unsigned nb = (unsigned)((buf^1) * 128*TST) * 4u;
#pragma unroll
            for (int i = 0; i < 4; i++) {
                int r = lr + i*32;
                unsigned da = sa + nb + (unsigned)(r*TST + lc4) * 4u;
                unsigned db = sb + nb + (unsigned)(r*TST + lc4) * 4u;
                asm volatile("cp.async.cg.shared.global [%0], [%1], 16;"
                             :: "r"(da), "l"(Ab + (size_t)r * K + k0 + 32 + lc4) : "memory");
                asm volatile("cp.async.cg.shared.global [%0], [%1], 16;"
                             :: "r"(db), "l"(Wb + (size_t)r * K + k0 + 32 + lc4) : "memory");
            }
            asm volatile("cp.async.commit_group;" ::: "memory");
        }

        const unsigned* Ac = As + buf*128*TST;
        const unsigned* Bc = Bs + buf*128*TST;
#pragma unroll
        for (int k8 = 0; k8 < 4; k8++) {
            const int kb = k8 * 8;
            unsigned af[2][4];
#pragma unroll
            for (int mf = 0; mf < 2; mf++) {
                int mrow = wm + mf*16 + grp;
                af[mf][0] = Ac[(mrow  )*TST + kb + tig];
                af[mf][1] = Ac[(mrow+8)*TST + kb + tig];
                af[mf][2] = Ac[(mrow  )*TST + kb + tig + 4];
                af[mf][3] = Ac[(mrow+8)*TST + kb + tig + 4];
            }
#pragma unroll
            for (int nf = 0; nf < 8; nf++) {
                int n = wn + nf*8 + grp;
                unsigned b0 = Bc[n*TST + kb + tig];
                unsigned b1 = Bc[n*TST + kb + tig + 4];
#pragma unroll
                for (int mf = 0; mf < 2; mf++) {
                    float* c0 = &acc[mf][nf][0];
                    asm volatile(
                        "mma.sync.aligned.m16n8k8.row.col.f32.tf32.tf32.f32 "
                        "{%0,%1,%2,%3}, {%4,%5,%6,%7}, {%8,%9}, {%0,%1,%2,%3};"
                        : "+f"(c0[0]), "+f"(c0[1]), "+f"(c0[2]), "+f"(c0[3])
                        : "r"(af[mf][0]), "r"(af[mf][1]), "r"(af[mf][2]), "r"(af[mf][3]),
                          "r"(b0), "r"(b1));
                }
            }
        }
        buf ^= 1;
    }

    // Optional fused RoPE: lo cols are nf<4 (i = nf*8+tig*2 < 32), hi = nf+4.
    if (rope) {
#pragma unroll
        for (int mf = 0; mf < 2; mf++) {
#pragma unroll
            for (int nf = 0; nf < 4; nf++) {
                const int i0 = nf*8 + tig*2;
#pragma unroll
                for (int hh = 0; hh < 2; hh++) {
                    int row = blockIdx.y*128 + wm + mf*16 + grp + hh*8;
                    int s   = row & (S_ - 1);
#pragma unroll
                    for (int j = 0; j < 2; j++) {
                        float c  = cosT[s*HD + i0 + j];
                        float sn = sinT[s*HD + i0 + j];
                        float L = acc[mf][nf  ][hh*2 + j];
                        float H = acc[mf][nf+4][hh*2 + j];
                        acc[mf][nf  ][hh*2 + j] = L*c - H*sn;
                        acc[mf][nf+4][hh*2 + j] = H*c + L*sn;
                    }
                }
            }
        }
    }

#pragma unroll
    for (int mf = 0; mf < 2; mf++) {
#pragma unroll
        for (int nf = 0; nf < 8; nf++) {
            float* c0 = &acc[mf][nf][0];
            int row = blockIdx.y*128 + wm + mf*16 + grp;
            int col = bx*128 + wn + nf*8 + tig*2;
            *(float2*)(C + (size_t)row*N + col)     = make_float2(c0[0], c0[1]);
            *(float2*)(C + (size_t)(row+8)*N + col) = make_float2(c0[2], c0[3]);
        }
    }
}

// ---------------------------------------------------------------------------
// Tensor-core causal flash attention v3 (tf32 mma.sync) -- exact R5/R8 code
// (measured 155.5us), except the epilogue stores tf32-rounded values so the
// wo GEMM can consume them directly (bit-identical to R8's load-time cvt).
// ---------------------------------------------------------------------------
#define FST 68
#define FA_SMEM ((64*FST*2 + 128*FST) * 4)   // Ks + Vs + Ps = 69632 B

__global__ __launch_bounds__(128) void flash_attn_mma3(
    const float* __restrict__ Q, const float* __restrict__ K,
    const float* __restrict__ V, float* __restrict__ O)
{
    extern __shared__ unsigned fsm[];
    unsigned* Ks = fsm;              // [64][FST]
    unsigned* Vs = Ks + 64*FST;      // [64][FST]
    unsigned* Ps = Vs + 64*FST;      // [128][FST]

    const int h  = blockIdx.x;
    const int bm = (gridDim.y - 1) - blockIdx.y;   // heaviest blocks first
    const int b  = blockIdx.z;
    const int hk = h >> 2;                          // GQA
    const int t    = threadIdx.x;
    const int w    = t >> 5;
    const int lane = t & 31;
    const int grp  = lane >> 2;
    const int tig  = lane & 3;
    const int rb   = bm*128 + w*32;   // warp's first q row (global)

    // ---- Q fragments: 2 mf x 8 kb x 4 regs, scaled by 1/8, tf32
    unsigned qf[2][8][4];
#pragma unroll
    for (int mf = 0; mf < 2; mf++) {
        const float* q0 = Q + (((size_t)(b*S_ + rb + mf*16 + grp    )*NH + h) << 6);
        const float* q1 = Q + (((size_t)(b*S_ + rb + mf*16 + grp + 8)*NH + h) << 6);
#pragma unroll
        for (int kb = 0; kb < 8; kb++) {
            qf[mf][kb][0] = f2tf32(0.125f * q0[kb*8 + tig]);
            qf[mf][kb][1] = f2tf32(0.125f * q1[kb*8 + tig]);
            qf[mf][kb][2] = f2tf32(0.125f * q0[kb*8 + tig + 4]);
            qf[mf][kb][3] = f2tf32(0.125f * q1[kb*8 + tig + 4]);
        }
    }

    float oacc[2][8][4];
#pragma unroll
    for (int mf = 0; mf < 2; mf++)
#pragma unroll
        for (int nf = 0; nf < 8; nf++) {
            oacc[mf][nf][0]=0.f; oacc[mf][nf][1]=0.f;
            oacc[mf][nf][2]=0.f; oacc[mf][nf][3]=0.f;
        }
    float m[4]  = {-1e30f, -1e30f, -1e30f, -1e30f};
    float l[4]  = {0.f, 0.f, 0.f, 0.f};

    const int ntiles = 2*(bm + 1);
    for (int tile = 0; tile < ntiles; tile++) {
        __syncthreads();
        // ---- load K,V tile (64 keys x 64 dims), convert to tf32
#pragma unroll
        for (int i = 0; i < 8; i++) {
            int idx = t + i*128;
            int r   = idx >> 4;
            int c4  = (idx & 15) * 4;
            size_t gb = (((size_t)(b*S_ + tile*64 + r)*NKV + hk) << 6) + c4;
            float4 kv = *(const float4*)(K + gb);
            float4 vv = *(const float4*)(V + gb);
            unsigned* kd = &Ks[r*FST + c4];
            kd[0]=f2tf32(kv.x); kd[1]=f2tf32(kv.y); kd[2]=f2tf32(kv.z); kd[3]=f2tf32(kv.w);
            unsigned* vd = &Vs[r*FST + c4];
            vd[0]=f2tf32(vv.x); vd[1]=f2tf32(vv.y); vd[2]=f2tf32(vv.z); vd[3]=f2tf32(vv.w);
        }
        __syncthreads();

        // ---- S = (Q/8) K^T : per warp 32x64
        float sacc[2][8][4];
#pragma unroll
        for (int mf = 0; mf < 2; mf++)
#pragma unroll
            for (int nf = 0; nf < 8; nf++) {
                sacc[mf][nf][0]=0.f; sacc[mf][nf][1]=0.f;
                sacc[mf][nf][2]=0.f; sacc[mf][nf][3]=0.f;
            }
#pragma unroll
        for (int kb = 0; kb < 8; kb++) {
#pragma unroll
            for (int nf = 0; nf < 8; nf++) {
                unsigned b0 = Ks[(nf*8+grp)*FST + kb*8 + tig];
                unsigned b1 = Ks[(nf*8+grp)*FST + kb*8 + tig + 4];
#pragma unroll
                for (int mf = 0; mf < 2; mf++) {
                    float* c0 = &sacc[mf][nf][0];
                    asm volatile(
                        "mma.sync.aligned.m16n8k8.row.col.f32.tf32.tf32.f32 "
                        "{%0,%1,%2,%3}, {%4,%5,%6,%7}, {%8,%9}, {%0,%1,%2,%3};"
                        : "+f"(c0[0]), "+f"(c0[1]), "+f"(c0[2]), "+f"(c0[3])
                        : "r"(qf[mf][kb][0]), "r"(qf[mf][kb][1]),
                          "r"(qf[mf][kb][2]), "r"(qf[mf][kb][3]),
                          "r"(b0), "r"(b1));
                }
            }
        }

        // ---- online softmax on fragment layout
        const bool diag = (tile >= 2*bm);
        const int colb = tile*64;
#pragma unroll
        for (int mf = 0; mf < 2; mf++) {
            const int r0 = rb + mf*16 + grp;
            const int r1 = r0 + 8;
            float mt0 = -1e30f, mt1 = -1e30f;
#pragma unroll
            for (int nf = 0; nf < 8; nf++) {
                const int c0i = colb + nf*8 + tig*2;
                if (diag) {
                    if (c0i     > r0) sacc[mf][nf][0] = -1e30f;
                    if (c0i + 1 > r0) sacc[mf][nf][1] = -1e30f;
                    if (c0i     > r1) sacc[mf][nf][2] = -1e30f;
                    if (c0i + 1 > r1) sacc[mf][nf][3] = -1e30f;
                }
                mt0 = fmaxf(mt0, fmaxf(sacc[mf][nf][0], sacc[mf][nf][1]));
                mt1 = fmaxf(mt1, fmaxf(sacc[mf][nf][2], sacc[mf][nf][3]));
            }
            mt0 = fmaxf(mt0, __shfl_xor_sync(0xffffffffu, mt0, 1));
            mt0 = fmaxf(mt0, __shfl_xor_sync(0xffffffffu, mt0, 2));
            mt1 = fmaxf(mt1, __shfl_xor_sync(0xffffffffu, mt1, 1));
            mt1 = fmaxf(mt1, __shfl_xor_sync(0xffffffffu, mt1, 2));

            const float mn0 = fmaxf(m[mf*2  ], mt0);
            const float mn1 = fmaxf(m[mf*2+1], mt1);
            const float cr0 = __expf(m[mf*2  ] - mn0);
            const float cr1 = __expf(m[mf*2+1] - mn1);
            float ps0 = 0.f, ps1 = 0.f;

            unsigned* P0 = &Ps[(w*32 + mf*16 + grp)*FST + tig*2];
            unsigned* P1 = P0 + 8*FST;
#pragma unroll
            for (int nf = 0; nf < 8; nf++) {
                float p00 = __expf(sacc[mf][nf][0] - mn0);
                float p01 = __expf(sacc[mf][nf][1] - mn0);
                float p10 = __expf(sacc[mf][nf][2] - mn1);
                float p11 = __expf(sacc[mf][nf][3] - mn1);
                ps0 += p00 + p01;
                ps1 += p10 + p11;
                *(uint2*)(P0 + nf*8) = make_uint2(f2tf32(p00), f2tf32(p01));
                *(uint2*)(P1 + nf*8) = make_uint2(f2tf32(p10), f2tf32(p11));
            }
            ps0 += __shfl_xor_sync(0xffffffffu, ps0, 1);
            ps0 += __shfl_xor_sync(0xffffffffu, ps0, 2);
            ps1 += __shfl_xor_sync(0xffffffffu, ps1, 1);
            ps1 += __shfl_xor_sync(0xffffffffu, ps1, 2);
            l[mf*2  ] = l[mf*2  ]*cr0 + ps0;  m[mf*2  ] = mn0;
            l[mf*2+1] = l[mf*2+1]*cr1 + ps1;  m[mf*2+1] = mn1;
#pragma unroll
            for (int nf = 0; nf < 8; nf++) {
                oacc[mf][nf][0] *= cr0; oacc[mf][nf][1] *= cr0;
                oacc[mf][nf][2] *= cr1; oacc[mf][nf][3] *= cr1;
            }
        }
        __syncwarp();   // Ps region is warp-private

        // ---- O += P V
#pragma unroll
        for (int kb = 0; kb < 8; kb++) {
            unsigned a[2][4];
#pragma unroll
            for (int mf = 0; mf < 2; mf++) {
                const int pr = w*32 + mf*16 + grp;
                a[mf][0] = Ps[(pr    )*FST + kb*8 + tig];
                a[mf][1] = Ps[(pr + 8)*FST + kb*8 + tig];
                a[mf][2] = Ps[(pr    )*FST + kb*8 + tig + 4];
                a[mf][3] = Ps[(pr + 8)*FST + kb*8 + tig + 4];
            }
#pragma unroll
            for (int nf = 0; nf < 8; nf++) {
                unsigned b0 = Vs[(kb*8 + tig    )*FST + nf*8 + grp];
                unsigned b1 = Vs[(kb*8 + tig + 4)*FST + nf*8 + grp];
#pragma unroll
                for (int mf = 0; mf < 2; mf++) {
                    float* c0 = &oacc[mf][nf][0];
                    asm volatile(
                        "mma.sync.aligned.m16n8k8.row.col.f32.tf32.tf32.f32 "
                        "{%0,%1,%2,%3}, {%4,%5,%6,%7}, {%8,%9}, {%0,%1,%2,%3};"
                        : "+f"(c0[0]), "+f"(c0[1]), "+f"(c0[2]), "+f"(c0[3])
                        : "r"(a[mf][0]), "r"(a[mf][1]), "r"(a[mf][2]), "r"(a[mf][3]),
                          "r"(b0), "r"(b1));
                }
            }
        }
    }

    // ---- epilogue: O / l, stored tf32-rounded for the wo GEMM
#pragma unroll
    for (int mf = 0; mf < 2; mf++) {
        const float inv0 = 1.f / l[mf*2];
        const float inv1 = 1.f / l[mf*2+1];
        float* o0 = O + (((size_t)(b*S_ + rb + mf*16 + grp    )*NH + h) << 6) + tig*2;
        float* o1 = O + (((size_t)(b*S_ + rb + mf*16 + grp + 8)*NH + h) << 6) + tig*2;
#pragma unroll
        for (int nf = 0; nf < 8; nf++) {
            *(uint2*)(o0 + nf*8) = make_uint2(f2tf32(oacc[mf][nf][0]*inv0),
                                              f2tf32(oacc[mf][nf][1]*inv0));
            *(uint2*)(o1 + nf*8) = make_uint2(f2tf32(oacc[mf][nf][2]*inv1),
                                              f2tf32(oacc[mf][nf][3]*inv1));
        }
    }
}

// ---------------------------------------------------------------------------
extern "C" void kernel_launch(void* const* d_in, const int* in_sizes, int n_in,
                              void* d_out, int out_size)
{
    const float* x    = (const float*)d_in[0];
    const float* cosT = (const float*)d_in[1];
    const float* sinT = (const float*)d_in[2];
    const float* wq   = (const float*)d_in[3];
    const float* wk   = (const float*)d_in[4];
    const float* wv   = (const float*)d_in[5];
    const float* wo   = (const float*)d_in[6];
    float* out = (float*)d_out;

    float *Q, *K, *V, *Aat;
    unsigned *X, *Wq, *Wk, *Wv, *Wo;
    cudaGetSymbolAddress((void**)&Q,   g_Q);
    cudaGetSymbolAddress((void**)&K,   g_K);
    cudaGetSymbolAddress((void**)&V,   g_V);
    cudaGetSymbolAddress((void**)&Aat, g_A);
    cudaGetSymbolAddress((void**)&X,   g_X);
    cudaGetSymbolAddress((void**)&Wq,  g_Wq);
    cudaGetSymbolAddress((void**)&Wk,  g_Wk);
    cudaGetSymbolAddress((void**)&Wv,  g_Wv);
    cudaGetSymbolAddress((void**)&Wo,  g_Wo);

    static bool attr_set = false;
    if (!attr_set) {
        cudaFuncSetAttribute(sgemm_tf32, cudaFuncAttributeMaxDynamicSharedMemorySize, GEMM_SMEM);
        cudaFuncSetAttribute(flash_attn_mma3, cudaFuncAttributeMaxDynamicSharedMemorySize, FA_SMEM);
        attr_set = true;
    }

    // One-shot tf32 conversion of x + weights
    conv_tf32<<<CONV_BLOCKS, 256>>>(x, wq, wk, wv, wo, X, Wq, Wk, Wv, Wo);

    // Q projection (rope fused) -- 256 CTAs = one wave at 2 CTA/SM
    sgemm_tf32<<<dim3(HID/128, MROWS/128), 256, GEMM_SMEM>>>(
        X, Wq, Q, HID/128, 1, nullptr, nullptr, 0,
        MROWS, HID, HID, cosT, sinT);

    // K (rope) + V projections merged into one launch -- 128 CTAs, one wave
    sgemm_tf32<<<dim3(2*(NKV*HD)/128, MROWS/128), 256, GEMM_SMEM>>>(
        X, Wk, K, (NKV*HD)/128, 1, Wv, V, 0,
        MROWS, NKV*HD, HID, cosT, sinT);

    // Tensor-core causal GQA flash attention
    flash_attn_mma3<<<dim3(NH, S_/128, B_), 128, FA_SMEM>>>(Q, K, V, Aat);

    // Output projection (Aat already tf32-rounded by the flash epilogue)
    sgemm_tf32<<<dim3(HID/128, MROWS/128), 256, GEMM_SMEM>>>(
        (const unsigned*)Aat, Wo, out, HID/128, 0, nullptr, nullptr, 0,
        MROWS, HID, HID, cosT, sinT);
}

// round 13
// speedup vs baseline: 1.4276x; 1.1054x over previous
#include <cuda_runtime.h>
#include <cuda_fp16.h>
#include <math.h>

#define B_  2
#define S_  2048
#define HID 1024
#define NH  16
#define NKV 4
#define HD  64
#define MROWS (B_*S_)   // 4096

// Scratch (no cudaMalloc allowed)
__device__ float g_Q[MROWS * HID];        // [B,S,NH,HD]
__device__ float g_K[MROWS * NKV * HD];   // [B,S,NKV,HD]
__device__ float g_V[MROWS * NKV * HD];
__device__ float g_A[MROWS * HID];        // attention output (tf32-rounded)
// tf32 (rna) pre-converted inputs
__device__ unsigned g_X [MROWS * HID];
__device__ unsigned g_Wq[HID * HID];
__device__ unsigned g_Wk[NKV * HD * HID];
__device__ unsigned g_Wv[NKV * HD * HID];
__device__ unsigned g_Wo[HID * HID];

__device__ __forceinline__ unsigned f2tf32(float x) {
    unsigned r;
    asm("cvt.rna.tf32.f32 %0, %1;" : "=r"(r) : "f"(x));
    return r;
}

__device__ __forceinline__ unsigned pack_h2(float a, float b) {
    __half2 h = __floats2half2_rn(a, b);
    return *(unsigned*)&h;
}

__device__ __forceinline__ unsigned smem_u32(const void* p) {
    unsigned a;
    asm("{ .reg .u64 t; cvta.to.shared.u64 t, %1; cvt.u32.u64 %0, t; }"
        : "=r"(a) : "l"(p));
    return a;
}

// ---------------------------------------------------------------------------
// One-shot tf32 (rna) conversion of x and the four weight matrices. (R12)
// ---------------------------------------------------------------------------
__global__ void conv_tf32(const float* __restrict__ x,  const float* __restrict__ wq,
                          const float* __restrict__ wk, const float* __restrict__ wv,
                          const float* __restrict__ wo,
                          unsigned* __restrict__ X,  unsigned* __restrict__ Wq,
                          unsigned* __restrict__ Wk, unsigned* __restrict__ Wv,
                          unsigned* __restrict__ Wo)
{
    int blk = blockIdx.x;
    const float* src; unsigned* dst; int base;
    if      (blk < 4096) { src = x;  dst = X;  base = blk; }
    else if (blk < 5120) { src = wq; dst = Wq; base = blk - 4096; }
    else if (blk < 5376) { src = wk; dst = Wk; base = blk - 5120; }
    else if (blk < 5632) { src = wv; dst = Wv; base = blk - 5376; }
    else                 { src = wo; dst = Wo; base = blk - 5632; }
    int idx = base * 1024 + threadIdx.x * 4;
    float4 v = *(const float4*)(src + idx);
    *(uint4*)(dst + idx) = make_uint4(f2tf32(v.x), f2tf32(v.y), f2tf32(v.z), f2tf32(v.w));
}
#define CONV_BLOCKS (4096 + 1024 + 256 + 256 + 1024)

// ---------------------------------------------------------------------------
// tf32 tensor-core GEMM (mma.sync m16n8k8) -- exact R12 (measured).
// ---------------------------------------------------------------------------
#define TST 36
#define GEMM_SMEM (2 * 2 * 128 * TST * 4)   // 73728 B dynamic

__global__ __launch_bounds__(256) void sgemm_tf32(
    const unsigned* __restrict__ A,
    const unsigned* __restrict__ W1, float* __restrict__ C1, int nx1, int rope1,
    const unsigned* __restrict__ W2, float* __restrict__ C2, int rope2,
    int M, int N, int K,
    const float* __restrict__ cosT, const float* __restrict__ sinT)
{
    extern __shared__ unsigned gsm[];
    unsigned* As = gsm;                 // [2][128*TST]
    unsigned* Bs = gsm + 2*128*TST;     // [2][128*TST]

    int bx = blockIdx.x;
    const unsigned* W; float* C; int rope;
    if (bx < nx1) { W = W1; C = C1; rope = rope1; }
    else          { W = W2; C = C2; rope = rope2; bx -= nx1; }

    const int t    = threadIdx.x;
    const int wid  = t >> 5;
    const int lane = t & 31;
    const int grp  = lane >> 2;
    const int tig  = lane & 3;
    const int wm   = (wid >> 1) * 32;
    const int wn   = (wid & 1) * 64;

    const int lr  = t >> 3;
    const int lc4 = (t & 7) * 4;

    const unsigned* Ab = A + (size_t)(blockIdx.y * 128) * K;
    const unsigned* Wb = W + (size_t)(bx * 128) * K;

    const unsigned sa = smem_u32(As);
    const unsigned sb = smem_u32(Bs);

    float acc[2][8][4];
#pragma unroll
    for (int mf = 0; mf < 2; mf++)
#pragma unroll
        for (int nf = 0; nf < 8; nf++) {
            acc[mf][nf][0]=0.f; acc[mf][nf][1]=0.f;
            acc[mf][nf][2]=0.f; acc[mf][nf][3]=0.f;
        }

#pragma unroll
    for (int i = 0; i < 4; i++) {
        int r = lr + i*32;
        unsigned da = sa + (unsigned)(r*TST + lc4) * 4u;
        unsigned db = sb + (unsigned)(r*TST + lc4) * 4u;
        asm volatile("cp.async.cg.shared.global [%0], [%1], 16;"
                     :: "r"(da), "l"(Ab + (size_t)r * K + lc4) : "memory");
        asm volatile("cp.async.cg.shared.global [%0], [%1], 16;"
                     :: "r"(db), "l"(Wb + (size_t)r * K + lc4) : "memory");
    }
    asm volatile("cp.async.commit_group;" ::: "memory");

    int buf = 0;
    for (int k0 = 0; k0 < K; k0 += 32) {
        const bool more = (k0 + 32 < K);
        asm volatile("cp.async.wait_group 0;" ::: "memory");
        __syncthreads();

        if (more) {
            const unsigned nb = (unsigned)((buf^1) * 128*TST) * 4u;
#pragma unroll
            for (int i = 0; i < 4; i++) {
                int r = lr + i*32;
                unsigned da = sa + nb + (unsigned)(r*TST + lc4) * 4u;
                unsigned db = sb + nb + (unsigned)(r*TST + lc4) * 4u;
                asm volatile("cp.async.cg.shared.global [%0], [%1], 16;"
                             :: "r"(da), "l"(Ab + (size_t)r * K + k0 + 32 + lc4) : "memory");
                asm volatile("cp.async.cg.shared.global [%0], [%1], 16;"
                             :: "r"(db), "l"(Wb + (size_t)r * K + k0 + 32 + lc4) : "memory");
            }
            asm volatile("cp.async.commit_group;" ::: "memory");
        }

        const unsigned* Ac = As + buf*128*TST;
        const unsigned* Bc = Bs + buf*128*TST;
#pragma unroll
        for (int k8 = 0; k8 < 4; k8++) {
            const int kb = k8 * 8;
            unsigned af[2][4];
#pragma unroll
            for (int mf = 0; mf < 2; mf++) {
                int mrow = wm + mf*16 + grp;
                af[mf][0] = Ac[(mrow  )*TST + kb + tig];
                af[mf][1] = Ac[(mrow+8)*TST + kb + tig];
                af[mf][2] = Ac[(mrow  )*TST + kb + tig + 4];
                af[mf][3] = Ac[(mrow+8)*TST + kb + tig + 4];
            }
#pragma unroll
            for (int nf = 0; nf < 8; nf++) {
                int n = wn + nf*8 + grp;
                unsigned b0 = Bc[n*TST + kb + tig];
                unsigned b1 = Bc[n*TST + kb + tig + 4];
#pragma unroll
                for (int mf = 0; mf < 2; mf++) {
                    float* c0 = &acc[mf][nf][0];
                    asm volatile(
                        "mma.sync.aligned.m16n8k8.row.col.f32.tf32.tf32.f32 "
                        "{%0,%1,%2,%3}, {%4,%5,%6,%7}, {%8,%9}, {%0,%1,%2,%3};"
                        : "+f"(c0[0]), "+f"(c0[1]), "+f"(c0[2]), "+f"(c0[3])
                        : "r"(af[mf][0]), "r"(af[mf][1]), "r"(af[mf][2]), "r"(af[mf][3]),
                          "r"(b0), "r"(b1));
                }
            }
        }
        buf ^= 1;
    }

    if (rope) {
#pragma unroll
        for (int mf = 0; mf < 2; mf++) {
#pragma unroll
            for (int nf = 0; nf < 4; nf++) {
                const int i0 = nf*8 + tig*2;
#pragma unroll
                for (int hh = 0; hh < 2; hh++) {
                    int row = blockIdx.y*128 + wm + mf*16 + grp + hh*8;
                    int s   = row & (S_ - 1);
#pragma unroll
                    for (int j = 0; j < 2; j++) {
                        float c  = cosT[s*HD + i0 + j];
                        float sn = sinT[s*HD + i0 + j];
                        float L = acc[mf][nf  ][hh*2 + j];
                        float H = acc[mf][nf+4][hh*2 + j];
                        acc[mf][nf  ][hh*2 + j] = L*c - H*sn;
                        acc[mf][nf+4][hh*2 + j] = H*c + L*sn;
                    }
                }
            }
        }
    }

#pragma unroll
    for (int mf = 0; mf < 2; mf++) {
#pragma unroll
        for (int nf = 0; nf < 8; nf++) {
            float* c0 = &acc[mf][nf][0];
            int row = blockIdx.y*128 + wm + mf*16 + grp;
            int col = bx*128 + wn + nf*8 + tig*2;
            *(float2*)(C + (size_t)row*N + col)     = make_float2(c0[0], c0[1]);
            *(float2*)(C + (size_t)(row+8)*N + col) = make_float2(c0[2], c0[3]);
        }
    }
}

// ---------------------------------------------------------------------------
// fp16 tensor-core causal flash attention (mma.sync m16n8k16, fp32 accum).
// Same structure as the measured R5 flash (128 threads, BM=128, BN=64,
// 32 q-rows/warp, Q in registers, P through smem) but all MMA operands fp16:
//   - Q/K/P/V as half2-packed fragments (fp16 eff. mantissa == tf32's 11 bits)
//   - half the MMA count (k16), half the smem, half the fragment LDS traffic
//   - V stored TRANSPOSED in smem (Vt[dim][key]) so PV B-frags are half2 words
// Strides 36 words/row keep every fragment access conflict-free (4*grp+tig).
// ---------------------------------------------------------------------------
#define KSW 36    // K row stride, half2 words
#define VSW 36    // Vt dim-row stride, half2 words
#define PSW 36    // P row stride, half2 words
#define FA_SMEM ((64*KSW + 64*VSW + 128*PSW) * 4)   // 36864 B

__global__ __launch_bounds__(128) void flash_attn_fp16(
    const float* __restrict__ Q, const float* __restrict__ K,
    const float* __restrict__ V, float* __restrict__ O)
{
    extern __shared__ unsigned fsm[];
    unsigned* Ksw = fsm;               // [64][KSW]  half2 words, [key][dim]
    unsigned* Vtw = Ksw + 64*KSW;      // [64][VSW]  half2 words, [dim][key]
    unsigned* Psw = Vtw + 64*VSW;      // [128][PSW] half2 words, [row][key]

    const int h  = blockIdx.x;
    const int bm = (gridDim.y - 1) - blockIdx.y;   // heaviest blocks first
    const int b  = blockIdx.z;
    const int hk = h >> 2;                          // GQA
    const int t    = threadIdx.x;
    const int w    = t >> 5;
    const int lane = t & 31;
    const int grp  = lane >> 2;
    const int tig  = lane & 3;
    const int rb   = bm*128 + w*32;   // warp's first q row (global)

    // ---- Q fragments: 2 mf x 4 k16-chunks x 4 half2 regs, scaled by 1/8
    unsigned qf[2][4][4];
#pragma unroll
    for (int mf = 0; mf < 2; mf++) {
        const float* q0 = Q + (((size_t)(b*S_ + rb + mf*16 + grp    )*NH + h) << 6);
        const float* q1 = Q + (((size_t)(b*S_ + rb + mf*16 + grp + 8)*NH + h) << 6);
#pragma unroll
        for (int c = 0; c < 4; c++) {
            float2 u0 = *(const float2*)(q0 + c*16 + 2*tig);
            float2 u1 = *(const float2*)(q1 + c*16 + 2*tig);
            float2 v0 = *(const float2*)(q0 + c*16 + 2*tig + 8);
            float2 v1 = *(const float2*)(q1 + c*16 + 2*tig + 8);
            qf[mf][c][0] = pack_h2(0.125f*u0.x, 0.125f*u0.y);
            qf[mf][c][1] = pack_h2(0.125f*u1.x, 0.125f*u1.y);
            qf[mf][c][2] = pack_h2(0.125f*v0.x, 0.125f*v0.y);
            qf[mf][c][3] = pack_h2(0.125f*v1.x, 0.125f*v1.y);
        }
    }

    float oacc[2][8][4];
#pragma unroll
    for (int mf = 0; mf < 2; mf++)
#pragma unroll
        for (int nf = 0; nf < 8; nf++) {
            oacc[mf][nf][0]=0.f; oacc[mf][nf][1]=0.f;
            oacc[mf][nf][2]=0.f; oacc[mf][nf][3]=0.f;
        }
    float m[4]  = {-1e30f, -1e30f, -1e30f, -1e30f};
    float l[4]  = {0.f, 0.f, 0.f, 0.f};

    const int ntiles = 2*(bm + 1);
    for (int tile = 0; tile < ntiles; tile++) {
        __syncthreads();
        // ---- K tile: [key][dim] halves
#pragma unroll
        for (int i = 0; i < 8; i++) {
            int idx = t + i*128;
            int r   = idx >> 4;
            int c4  = (idx & 15) * 4;
            size_t gb = (((size_t)(b*S_ + tile*64 + r)*NKV + hk) << 6) + c4;
            float4 kv = *(const float4*)(K + gb);
            Ksw[r*KSW + (c4 >> 1)    ] = pack_h2(kv.x, kv.y);
            Ksw[r*KSW + (c4 >> 1) + 1] = pack_h2(kv.z, kv.w);
        }
        // ---- V tile transposed: Vt[dim][key-pair] half2 = {V[2kp][d], V[2kp+1][d]}
#pragma unroll
        for (int i = 0; i < 8; i++) {
            int lin = t + i*128;          // 0..1023
            int kp  = lin >> 5;           // key pair 0..31
            int d2  = lin & 31;           // dim pair 0..31
            size_t gb0 = (((size_t)(b*S_ + tile*64 + 2*kp)*NKV + hk) << 6) + 2*d2;
            float2 va = *(const float2*)(V + gb0);
            float2 vb = *(const float2*)(V + gb0 + (NKV << 6));
            Vtw[(2*d2  )*VSW + kp] = pack_h2(va.x, vb.x);
            Vtw[(2*d2+1)*VSW + kp] = pack_h2(va.y, vb.y);
        }
        __syncthreads();

        // ---- S = (Q/8) K^T : per warp 32x64, fp16 k16 MMAs
        float sacc[2][8][4];
#pragma unroll
        for (int mf = 0; mf < 2; mf++)
#pragma unroll
            for (int nf = 0; nf < 8; nf++) {
                sacc[mf][nf][0]=0.f; sacc[mf][nf][1]=0.f;
                sacc[mf][nf][2]=0.f; sacc[mf][nf][3]=0.f;
            }
#pragma unroll
        for (int c = 0; c < 4; c++) {
#pragma unroll
            for (int nf = 0; nf < 8; nf++) {
                unsigned b0 = Ksw[(nf*8+grp)*KSW + c*8 + tig];
                unsigned b1 = Ksw[(nf*8+grp)*KSW + c*8 + tig + 4];
#pragma unroll
                for (int mf = 0; mf < 2; mf++) {
                    float* c0 = &sacc[mf][nf][0];
                    asm volatile(
                        "mma.sync.aligned.m16n8k16.row.col.f32.f16.f16.f32 "
                        "{%0,%1,%2,%3}, {%4,%5,%6,%7}, {%8,%9}, {%0,%1,%2,%3};"
                        : "+f"(c0[0]), "+f"(c0[1]), "+f"(c0[2]), "+f"(c0[3])
                        : "r"(qf[mf][c][0]), "r"(qf[mf][c][1]),
                          "r"(qf[mf][c][2]), "r"(qf[mf][c][3]),
                          "r"(b0), "r"(b1));
                }
            }
        }

        // ---- online softmax on fragment layout (identical to tf32 version)
        const bool diag = (tile >= 2*bm);
        const int colb = tile*64;
#pragma unroll
        for (int mf = 0; mf < 2; mf++) {
            const int r0 = rb + mf*16 + grp;
            const int r1 = r0 + 8;
            float mt0 = -1e30f, mt1 = -1e30f;
#pragma unroll
            for (int nf = 0; nf < 8; nf++) {
                const int c0i = colb + nf*8 + tig*2;
                if (diag) {
                    if (c0i     > r0) sacc[mf][nf][0] = -1e30f;
                    if (c0i + 1 > r0) sacc[mf][nf][1] = -1e30f;
                    if (c0i     > r1) sacc[mf][nf][2] = -1e30f;
                    if (c0i + 1 > r1) sacc[mf][nf][3] = -1e30f;
                }
                mt0 = fmaxf(mt0, fmaxf(sacc[mf][nf][0], sacc[mf][nf][1]));
                mt1 = fmaxf(mt1, fmaxf(sacc[mf][nf][2], sacc[mf][nf][3]));
            }
            mt0 = fmaxf(mt0, __shfl_xor_sync(0xffffffffu, mt0, 1));
            mt0 = fmaxf(mt0, __shfl_xor_sync(0xffffffffu, mt0, 2));
            mt1 = fmaxf(mt1, __shfl_xor_sync(0xffffffffu, mt1, 1));
            mt1 = fmaxf(mt1, __shfl_xor_sync(0xffffffffu, mt1, 2));

            const float mn0 = fmaxf(m[mf*2  ], mt0);
            const float mn1 = fmaxf(m[mf*2+1], mt1);
            const float cr0 = __expf(m[mf*2  ] - mn0);
            const float cr1 = __expf(m[mf*2+1] - mn1);
            float ps0 = 0.f, ps1 = 0.f;

            unsigned* P0 = &Psw[(w*32 + mf*16 + grp)*PSW + tig];
            unsigned* P1 = P0 + 8*PSW;
#pragma unroll
            for (int nf = 0; nf < 8; nf++) {
                float p00 = __expf(sacc[mf][nf][0] - mn0);
                float p01 = __expf(sacc[mf][nf][1] - mn0);
                float p10 = __expf(sacc[mf][nf][2] - mn1);
                float p11 = __expf(sacc[mf][nf][3] - mn1);
                ps0 += p00 + p01;
                ps1 += p10 + p11;
                P0[nf*4] = pack_h2(p00, p01);   // cols nf*8+2tig, +1
                P1[nf*4] = pack_h2(p10, p11);
            }
            ps0 += __shfl_xor_sync(0xffffffffu, ps0, 1);
            ps0 += __shfl_xor_sync(0xffffffffu, ps0, 2);
            ps1 += __shfl_xor_sync(0xffffffffu, ps1, 1);
            ps1 += __shfl_xor_sync(0xffffffffu, ps1, 2);
            l[mf*2  ] = l[mf*2  ]*cr0 + ps0;  m[mf*2  ] = mn0;
            l[mf*2+1] = l[mf*2+1]*cr1 + ps1;  m[mf*2+1] = mn1;
#pragma unroll
            for (int nf = 0; nf < 8; nf++) {
                oacc[mf][nf][0] *= cr0; oacc[mf][nf][1] *= cr0;
                oacc[mf][nf][2] *= cr1; oacc[mf][nf][3] *= cr1;
            }
        }
        __syncwarp();   // Psw region is warp-private

        // ---- O += P V : 4 k16 key-chunks, fp16 MMAs
#pragma unroll
        for (int kb = 0; kb < 4; kb++) {
            unsigned a[2][4];
#pragma unroll
            for (int mf = 0; mf < 2; mf++) {
                const int pr = w*32 + mf*16 + grp;
                a[mf][0] = Psw[(pr    )*PSW + kb*8 + tig];
                a[mf][1] = Psw[(pr + 8)*PSW + kb*8 + tig];
                a[mf][2] = Psw[(pr    )*PSW + kb*8 + tig + 4];
                a[mf][3] = Psw[(pr + 8)*PSW + kb*8 + tig + 4];
            }
#pragma unroll
            for (int nf = 0; nf < 8; nf++) {
                unsigned b0 = Vtw[(nf*8+grp)*VSW + kb*8 + tig];
                unsigned b1 = Vtw[(nf*8+grp)*VSW + kb*8 + tig + 4];
#pragma unroll
                for (int mf = 0; mf < 2; mf++) {
                    float* c0 = &oacc[mf][nf][0];
                    asm volatile(
                        "mma.sync.aligned.m16n8k16.row.col.f32.f16.f16.f32 "
                        "{%0,%1,%2,%3}, {%4,%5,%6,%7}, {%8,%9}, {%0,%1,%2,%3};"
                        : "+f"(c0[0]), "+f"(c0[1]), "+f"(c0[2]), "+f"(c0[3])
                        : "r"(a[mf][0]), "r"(a[mf][1]), "r"(a[mf][2]), "r"(a[mf][3]),
                          "r"(b0), "r"(b1));
                }
            }
        }
    }

    // ---- epilogue: O / l, stored tf32-rounded for the wo GEMM
#pragma unroll
    for (int mf = 0; mf < 2; mf++) {
        const float inv0 = 1.f / l[mf*2];
        const float inv1 = 1.f / l[mf*2+1];
        float* o0 = O + (((size_t)(b*S_ + rb + mf*16 + grp    )*NH + h) << 6) + tig*2;
        float* o1 = O + (((size_t)(b*S_ + rb + mf*16 + grp + 8)*NH + h) << 6) + tig*2;
#pragma unroll
        for (int nf = 0; nf < 8; nf++) {
            *(uint2*)(o0 + nf*8) = make_uint2(f2tf32(oacc[mf][nf][0]*inv0),
                                              f2tf32(oacc[mf][nf][1]*inv0));
            *(uint2*)(o1 + nf*8) = make_uint2(f2tf32(oacc[mf][nf][2]*inv1),
                                              f2tf32(oacc[mf][nf][3]*inv1));
        }
    }
}

// ---------------------------------------------------------------------------
extern "C" void kernel_launch(void* const* d_in, const int* in_sizes, int n_in,
                              void* d_out, int out_size)
{
    const float* x    = (const float*)d_in[0];
    const float* cosT = (const float*)d_in[1];
    const float* sinT = (const float*)d_in[2];
    const float* wq   = (const float*)d_in[3];
    const float* wk   = (const float*)d_in[4];
    const float* wv   = (const float*)d_in[5];
    const float* wo   = (const float*)d_in[6];
    float* out = (float*)d_out;

    float *Q, *K, *V, *Aat;
    unsigned *X, *Wq, *Wk, *Wv, *Wo;
    cudaGetSymbolAddress((void**)&Q,   g_Q);
    cudaGetSymbolAddress((void**)&K,   g_K);
    cudaGetSymbolAddress((void**)&V,   g_V);
    cudaGetSymbolAddress((void**)&Aat, g_A);
    cudaGetSymbolAddress((void**)&X,   g_X);
    cudaGetSymbolAddress((void**)&Wq,  g_Wq);
    cudaGetSymbolAddress((void**)&Wk,  g_Wk);
    cudaGetSymbolAddress((void**)&Wv,  g_Wv);
    cudaGetSymbolAddress((void**)&Wo,  g_Wo);

    static bool attr_set = false;
    if (!attr_set) {
        cudaFuncSetAttribute(sgemm_tf32, cudaFuncAttributeMaxDynamicSharedMemorySize, GEMM_SMEM);
        cudaFuncSetAttribute(flash_attn_fp16, cudaFuncAttributeMaxDynamicSharedMemorySize, FA_SMEM);
        attr_set = true;
    }

    // One-shot tf32 conversion of x + weights
    conv_tf32<<<CONV_BLOCKS, 256>>>(x, wq, wk, wv, wo, X, Wq, Wk, Wv, Wo);

    // Q projection (rope fused) -- 256 CTAs = one wave at 2 CTA/SM
    sgemm_tf32<<<dim3(HID/128, MROWS/128), 256, GEMM_SMEM>>>(
        X, Wq, Q, HID/128, 1, nullptr, nullptr, 0,
        MROWS, HID, HID, cosT, sinT);

    // K (rope) + V projections merged into one launch -- 128 CTAs, one wave
    sgemm_tf32<<<dim3(2*(NKV*HD)/128, MROWS/128), 256, GEMM_SMEM>>>(
        X, Wk, K, (NKV*HD)/128, 1, Wv, V, 0,
        MROWS, NKV*HD, HID, cosT, sinT);

    // fp16 tensor-core causal GQA flash attention
    flash_attn_fp16<<<dim3(NH, S_/128, B_), 128, FA_SMEM>>>(Q, K, V, Aat);

    // Output projection (Aat already tf32-rounded by the flash epilogue)
    sgemm_tf32<<<dim3(HID/128, MROWS/128), 256, GEMM_SMEM>>>(
        (const unsigned*)Aat, Wo, out, HID/128, 0, nullptr, nullptr, 0,
        MROWS, HID, HID, cosT, sinT);
}

// round 14
// speedup vs baseline: 1.8709x; 1.3105x over previous
#include <cuda_runtime.h>
#include <cuda_fp16.h>
#include <math.h>

#define B_  2
#define S_  2048
#define HID 1024
#define NH  16
#define NKV 4
#define HD  64
#define MROWS (B_*S_)   // 4096

// Scratch (no cudaMalloc allowed)
__device__ float g_Q[MROWS * HID];            // [B,S,NH,HD] fp32
__device__ float g_K[MROWS * NKV * HD];       // fp32
__device__ float g_V[MROWS * NKV * HD];       // fp32
__device__ unsigned g_A [MROWS * HID / 2];    // attention out, half2 words
// fp16 pre-converted inputs (half2 words)
__device__ unsigned g_X [MROWS * HID / 2];
__device__ unsigned g_Wq[HID * HID / 2];
__device__ unsigned g_Wk[NKV * HD * HID / 2];
__device__ unsigned g_Wv[NKV * HD * HID / 2];
__device__ unsigned g_Wo[HID * HID / 2];

__device__ __forceinline__ unsigned pack_h2(float a, float b) {
    __half2 h = __floats2half2_rn(a, b);
    return *(unsigned*)&h;
}

__device__ __forceinline__ unsigned smem_u32(const void* p) {
    unsigned a;
    asm("{ .reg .u64 t; cvta.to.shared.u64 t, %1; cvt.u32.u64 %0, t; }"
        : "=r"(a) : "l"(p));
    return a;
}

// ---------------------------------------------------------------------------
// One-shot fp16 (rn) conversion of x and the four weight matrices.
// Segments (1024-float blocks): x 4096 | wq 1024 | wk 256 | wv 256 | wo 1024.
// ---------------------------------------------------------------------------
__global__ void conv_fp16(const float* __restrict__ x,  const float* __restrict__ wq,
                          const float* __restrict__ wk, const float* __restrict__ wv,
                          const float* __restrict__ wo,
                          unsigned* __restrict__ X,  unsigned* __restrict__ Wq,
                          unsigned* __restrict__ Wk, unsigned* __restrict__ Wv,
                          unsigned* __restrict__ Wo)
{
    int blk = blockIdx.x;
    const float* src; unsigned* dst; int base;
    if      (blk < 4096) { src = x;  dst = X;  base = blk; }
    else if (blk < 5120) { src = wq; dst = Wq; base = blk - 4096; }
    else if (blk < 5376) { src = wk; dst = Wk; base = blk - 5120; }
    else if (blk < 5632) { src = wv; dst = Wv; base = blk - 5376; }
    else                 { src = wo; dst = Wo; base = blk - 5632; }
    int idx = base * 1024 + threadIdx.x * 4;
    float4 v = *(const float4*)(src + idx);
    *(uint2*)(dst + (idx >> 1)) = make_uint2(pack_h2(v.x, v.y), pack_h2(v.z, v.w));
}
#define CONV_BLOCKS (4096 + 1024 + 256 + 256 + 1024)

// ---------------------------------------------------------------------------
// fp16 tensor-core GEMM (mma.sync m16n8k16, fp32 accum):
//   C[M,N] = A[M,K] @ W[N,K]^T,  A/W pre-converted half2 words.
// Same structure as the measured R12 GEMM (cp.async double-buffer, one sync
// per K-step, 256 threads, warp tile 32x64, dual-output mode) but fp16:
// half the MMAs, half the cp.async bytes, half the smem.
// Row stride 20 half2-words -> all fragment LDS conflict-free.
// ---------------------------------------------------------------------------
#define HST 20
#define GEMM_SMEM (2 * 2 * 128 * HST * 4)   // 40960 B dynamic

__global__ __launch_bounds__(256) void hgemm(
    const unsigned* __restrict__ A,
    const unsigned* __restrict__ W1, float* __restrict__ C1, int nx1, int rope1,
    const unsigned* __restrict__ W2, float* __restrict__ C2, int rope2,
    int M, int N, int K,    // K in halves (elements)
    const float* __restrict__ cosT, const float* __restrict__ sinT)
{
    extern __shared__ unsigned gsm[];
    unsigned* As = gsm;                 // [2][128*HST]
    unsigned* Bs = gsm + 2*128*HST;     // [2][128*HST]

    int bx = blockIdx.x;
    const unsigned* W; float* C; int rope;
    if (bx < nx1) { W = W1; C = C1; rope = rope1; }
    else          { W = W2; C = C2; rope = rope2; bx -= nx1; }

    const int t    = threadIdx.x;
    const int wid  = t >> 5;
    const int lane = t & 31;
    const int grp  = lane >> 2;
    const int tig  = lane & 3;
    const int wm   = (wid >> 1) * 32;   // 4 row-warps
    const int wn   = (wid & 1) * 64;    // 2 col-warps

    // loader: idx = t + i*256 (i<2): row r = idx>>2, word-chunk cs = (idx&3)*4
    const int lr = t >> 2;              // row base (0..63), +64 for i=1
    const int lcs = (t & 3) * 4;        // word offset in row (0,4,8,12)

    const int K2 = K >> 1;              // row stride in half2 words
    const unsigned* Ab = A + (size_t)(blockIdx.y * 128) * K2;
    const unsigned* Wb = W + (size_t)(bx * 128) * K2;

    const unsigned sa = smem_u32(As);
    const unsigned sb = smem_u32(Bs);

    float acc[2][8][4];
#pragma unroll
    for (int mf = 0; mf < 2; mf++)
#pragma unroll
        for (int nf = 0; nf < 8; nf++) {
            acc[mf][nf][0]=0.f; acc[mf][nf][1]=0.f;
            acc[mf][nf][2]=0.f; acc[mf][nf][3]=0.f;
        }

    // ---- preload K-tile 0 into buffer 0 (cp.async 16B; 2 chunks/op/thread)
#pragma unroll
    for (int i = 0; i < 2; i++) {
        int r = lr + i*64;
        unsigned da = sa + (unsigned)(r*HST + lcs) * 4u;
        unsigned db = sb + (unsigned)(r*HST + lcs) * 4u;
        asm volatile("cp.async.cg.shared.global [%0], [%1], 16;"
                     :: "r"(da), "l"(Ab + (size_t)r * K2 + lcs) : "memory");
        asm volatile("cp.async.cg.shared.global [%0], [%1], 16;"
                     :: "r"(db), "l"(Wb + (size_t)r * K2 + lcs) : "memory");
    }
    asm volatile("cp.async.commit_group;" ::: "memory");

    int buf = 0;
    for (int k0 = 0; k0 < K; k0 += 32) {      // 32 halves = 16 words per tile
        const bool more = (k0 + 32 < K);
        asm volatile("cp.async.wait_group 0;" ::: "memory");
        __syncthreads();

        if (more) {
            const unsigned nb = (unsigned)((buf^1) * 128*HST) * 4u;
            const int kw = (k0 + 32) >> 1;     // next tile word offset
#pragma unroll
            for (int i = 0; i < 2; i++) {
                int r = lr + i*64;
                unsigned da = sa + nb + (unsigned)(r*HST + lcs) * 4u;
                unsigned db = sb + nb + (unsigned)(r*HST + lcs) * 4u;
                asm volatile("cp.async.cg.shared.global [%0], [%1], 16;"
                             :: "r"(da), "l"(Ab + (size_t)r * K2 + kw + lcs) : "memory");
                asm volatile("cp.async.cg.shared.global [%0], [%1], 16;"
                             :: "r"(db), "l"(Wb + (size_t)r * K2 + kw + lcs) : "memory");
            }
            asm volatile("cp.async.commit_group;" ::: "memory");
        }

        const unsigned* Ac = As + buf*128*HST;
        const unsigned* Bc = Bs + buf*128*HST;
#pragma unroll
        for (int c = 0; c < 2; c++) {          // two k16 steps per tile
            const int kb = c * 8;
            unsigned af[2][4];
#pragma unroll
            for (int mf = 0; mf < 2; mf++) {
                int mrow = wm + mf*16 + grp;
                af[mf][0] = Ac[(mrow  )*HST + kb + tig];
                af[mf][1] = Ac[(mrow+8)*HST + kb + tig];
                af[mf][2] = Ac[(mrow  )*HST + kb + tig + 4];
                af[mf][3] = Ac[(mrow+8)*HST + kb + tig + 4];
            }
#pragma unroll
            for (int nf = 0; nf < 8; nf++) {
                int n = wn + nf*8 + grp;
                unsigned b0 = Bc[n*HST + kb + tig];
                unsigned b1 = Bc[n*HST + kb + tig + 4];
#pragma unroll
                for (int mf = 0; mf < 2; mf++) {
                    float* c0 = &acc[mf][nf][0];
                    asm volatile(
                        "mma.sync.aligned.m16n8k16.row.col.f32.f16.f16.f32 "
                        "{%0,%1,%2,%3}, {%4,%5,%6,%7}, {%8,%9}, {%0,%1,%2,%3};"
                        : "+f"(c0[0]), "+f"(c0[1]), "+f"(c0[2]), "+f"(c0[3])
                        : "r"(af[mf][0]), "r"(af[mf][1]), "r"(af[mf][2]), "r"(af[mf][3]),
                          "r"(b0), "r"(b1));
                }
            }
        }
        buf ^= 1;
    }

    // Optional fused RoPE (fragment layout identical to tf32 version)
    if (rope) {
#pragma unroll
        for (int mf = 0; mf < 2; mf++) {
#pragma unroll
            for (int nf = 0; nf < 4; nf++) {
                const int i0 = nf*8 + tig*2;
#pragma unroll
                for (int hh = 0; hh < 2; hh++) {
                    int row = blockIdx.y*128 + wm + mf*16 + grp + hh*8;
                    int s   = row & (S_ - 1);
#pragma unroll
                    for (int j = 0; j < 2; j++) {
                        float c  = cosT[s*HD + i0 + j];
                        float sn = sinT[s*HD + i0 + j];
                        float L = acc[mf][nf  ][hh*2 + j];
                        float H = acc[mf][nf+4][hh*2 + j];
                        acc[mf][nf  ][hh*2 + j] = L*c - H*sn;
                        acc[mf][nf+4][hh*2 + j] = H*c + L*sn;
                    }
                }
            }
        }
    }

#pragma unroll
    for (int mf = 0; mf < 2; mf++) {
#pragma unroll
        for (int nf = 0; nf < 8; nf++) {
            float* c0 = &acc[mf][nf][0];
            int row = blockIdx.y*128 + wm + mf*16 + grp;
            int col = bx*128 + wn + nf*8 + tig*2;
            *(float2*)(C + (size_t)row*N + col)     = make_float2(c0[0], c0[1]);
            *(float2*)(C + (size_t)(row+8)*N + col) = make_float2(c0[2], c0[3]);
        }
    }
}

// ---------------------------------------------------------------------------
// fp16 tensor-core causal flash attention (R13, measured 123.8us), epilogue
// now writes half2 Aat for the fp16 wo GEMM.
// ---------------------------------------------------------------------------
#define KSW 36
#define VSW 36
#define PSW 36
#define FA_SMEM ((64*KSW + 64*VSW + 128*PSW) * 4)   // 36864 B

__global__ __launch_bounds__(128) void flash_attn_fp16(
    const float* __restrict__ Q, const float* __restrict__ K,
    const float* __restrict__ V, unsigned* __restrict__ O)
{
    extern __shared__ unsigned fsm[];
    unsigned* Ksw = fsm;               // [64][KSW]  half2, [key][dim]
    unsigned* Vtw = Ksw + 64*KSW;      // [64][VSW]  half2, [dim][key]
    unsigned* Psw = Vtw + 64*VSW;      // [128][PSW] half2, [row][key]

    const int h  = blockIdx.x;
    const int bm = (gridDim.y - 1) - blockIdx.y;
    const int b  = blockIdx.z;
    const int hk = h >> 2;
    const int t    = threadIdx.x;
    const int w    = t >> 5;
    const int lane = t & 31;
    const int grp  = lane >> 2;
    const int tig  = lane & 3;
    const int rb   = bm*128 + w*32;

    unsigned qf[2][4][4];
#pragma unroll
    for (int mf = 0; mf < 2; mf++) {
        const float* q0 = Q + (((size_t)(b*S_ + rb + mf*16 + grp    )*NH + h) << 6);
        const float* q1 = Q + (((size_t)(b*S_ + rb + mf*16 + grp + 8)*NH + h) << 6);
#pragma unroll
        for (int c = 0; c < 4; c++) {
            float2 u0 = *(const float2*)(q0 + c*16 + 2*tig);
            float2 u1 = *(const float2*)(q1 + c*16 + 2*tig);
            float2 v0 = *(const float2*)(q0 + c*16 + 2*tig + 8);
            float2 v1 = *(const float2*)(q1 + c*16 + 2*tig + 8);
            qf[mf][c][0] = pack_h2(0.125f*u0.x, 0.125f*u0.y);
            qf[mf][c][1] = pack_h2(0.125f*u1.x, 0.125f*u1.y);
            qf[mf][c][2] = pack_h2(0.125f*v0.x, 0.125f*v0.y);
            qf[mf][c][3] = pack_h2(0.125f*v1.x, 0.125f*v1.y);
        }
    }

    float oacc[2][8][4];
#pragma unroll
    for (int mf = 0; mf < 2; mf++)
#pragma unroll
        for (int nf = 0; nf < 8; nf++) {
            oacc[mf][nf][0]=0.f; oacc[mf][nf][1]=0.f;
            oacc[mf][nf][2]=0.f; oacc[mf][nf][3]=0.f;
        }
    float m[4]  = {-1e30f, -1e30f, -1e30f, -1e30f};
    float l[4]  = {0.f, 0.f, 0.f, 0.f};

    const int ntiles = 2*(bm + 1);
    for (int tile = 0; tile < ntiles; tile++) {
        __syncthreads();
#pragma unroll
        for (int i = 0; i < 8; i++) {
            int idx = t + i*128;
            int r   = idx >> 4;
            int c4  = (idx & 15) * 4;
            size_t gb = (((size_t)(b*S_ + tile*64 + r)*NKV + hk) << 6) + c4;
            float4 kv = *(const float4*)(K + gb);
            Ksw[r*KSW + (c4 >> 1)    ] = pack_h2(kv.x, kv.y);
            Ksw[r*KSW + (c4 >> 1) + 1] = pack_h2(kv.z, kv.w);
        }
#pragma unroll
        for (int i = 0; i < 8; i++) {
            int lin = t + i*128;
            int kp  = lin >> 5;
            int d2  = lin & 31;
            size_t gb0 = (((size_t)(b*S_ + tile*64 + 2*kp)*NKV + hk) << 6) + 2*d2;
            float2 va = *(const float2*)(V + gb0);
            float2 vb = *(const float2*)(V + gb0 + (NKV << 6));
            Vtw[(2*d2  )*VSW + kp] = pack_h2(va.x, vb.x);
            Vtw[(2*d2+1)*VSW + kp] = pack_h2(va.y, vb.y);
        }
        __syncthreads();

        float sacc[2][8][4];
#pragma unroll
        for (int mf = 0; mf < 2; mf++)
#pragma unroll
            for (int nf = 0; nf < 8; nf++) {
                sacc[mf][nf][0]=0.f; sacc[mf][nf][1]=0.f;
                sacc[mf][nf][2]=0.f; sacc[mf][nf][3]=0.f;
            }
#pragma unroll
        for (int c = 0; c < 4; c++) {
#pragma unroll
            for (int nf = 0; nf < 8; nf++) {
                unsigned b0 = Ksw[(nf*8+grp)*KSW + c*8 + tig];
                unsigned b1 = Ksw[(nf*8+grp)*KSW + c*8 + tig + 4];
#pragma unroll
                for (int mf = 0; mf < 2; mf++) {
                    float* c0 = &sacc[mf][nf][0];
                    asm volatile(
                        "mma.sync.aligned.m16n8k16.row.col.f32.f16.f16.f32 "
                        "{%0,%1,%2,%3}, {%4,%5,%6,%7}, {%8,%9}, {%0,%1,%2,%3};"
                        : "+f"(c0[0]), "+f"(c0[1]), "+f"(c0[2]), "+f"(c0[3])
                        : "r"(qf[mf][c][0]), "r"(qf[mf][c][1]),
                          "r"(qf[mf][c][2]), "r"(qf[mf][c][3]),
                          "r"(b0), "r"(b1));
                }
            }
        }

        const bool diag = (tile >= 2*bm);
        const int colb = tile*64;
#pragma unroll
        for (int mf = 0; mf < 2; mf++) {
            const int r0 = rb + mf*16 + grp;
            const int r1 = r0 + 8;
            float mt0 = -1e30f, mt1 = -1e30f;
#pragma unroll
            for (int nf = 0; nf < 8; nf++) {
                const int c0i = colb + nf*8 + tig*2;
                if (diag) {
                    if (c0i     > r0) sacc[mf][nf][0] = -1e30f;
                    if (c0i + 1 > r0) sacc[mf][nf][1] = -1e30f;
                    if (c0i     > r1) sacc[mf][nf][2] = -1e30f;
                    if (c0i + 1 > r1) sacc[mf][nf][3] = -1e30f;
                }
                mt0 = fmaxf(mt0, fmaxf(sacc[mf][nf][0], sacc[mf][nf][1]));
                mt1 = fmaxf(mt1, fmaxf(sacc[mf][nf][2], sacc[mf][nf][3]));
            }
            mt0 = fmaxf(mt0, __shfl_xor_sync(0xffffffffu, mt0, 1));
            mt0 = fmaxf(mt0, __shfl_xor_sync(0xffffffffu, mt0, 2));
            mt1 = fmaxf(mt1, __shfl_xor_sync(0xffffffffu, mt1, 1));
            mt1 = fmaxf(mt1, __shfl_xor_sync(0xffffffffu, mt1, 2));

            const float mn0 = fmaxf(m[mf*2  ], mt0);
            const float mn1 = fmaxf(m[mf*2+1], mt1);
            const float cr0 = __expf(m[mf*2  ] - mn0);
            const float cr1 = __expf(m[mf*2+1] - mn1);
            float ps0 = 0.f, ps1 = 0.f;

            unsigned* P0 = &Psw[(w*32 + mf*16 + grp)*PSW + tig];
            unsigned* P1 = P0 + 8*PSW;
#pragma unroll
            for (int nf = 0; nf < 8; nf++) {
                float p00 = __expf(sacc[mf][nf][0] - mn0);
                float p01 = __expf(sacc[mf][nf][1] - mn0);
                float p10 = __expf(sacc[mf][nf][2] - mn1);
                float p11 = __expf(sacc[mf][nf][3] - mn1);
                ps0 += p00 + p01;
                ps1 += p10 + p11;
                P0[nf*4] = pack_h2(p00, p01);
                P1[nf*4] = pack_h2(p10, p11);
            }
            ps0 += __shfl_xor_sync(0xffffffffu, ps0, 1);
            ps0 += __shfl_xor_sync(0xffffffffu, ps0, 2);
            ps1 += __shfl_xor_sync(0xffffffffu, ps1, 1);
            ps1 += __shfl_xor_sync(0xffffffffu, ps1, 2);
            l[mf*2  ] = l[mf*2  ]*cr0 + ps0;  m[mf*2  ] = mn0;
            l[mf*2+1] = l[mf*2+1]*cr1 + ps1;  m[mf*2+1] = mn1;
#pragma unroll
            for (int nf = 0; nf < 8; nf++) {
                oacc[mf][nf][0] *= cr0; oacc[mf][nf][1] *= cr0;
                oacc[mf][nf][2] *= cr1; oacc[mf][nf][3] *= cr1;
            }
        }
        __syncwarp();

#pragma unroll
        for (int kb = 0; kb < 4; kb++) {
            unsigned a[2][4];
#pragma unroll
            for (int mf = 0; mf < 2; mf++) {
                const int pr = w*32 + mf*16 + grp;
                a[mf][0] = Psw[(pr    )*PSW + kb*8 + tig];
                a[mf][1] = Psw[(pr + 8)*PSW + kb*8 + tig];
                a[mf][2] = Psw[(pr    )*PSW + kb*8 + tig + 4];
                a[mf][3] = Psw[(pr + 8)*PSW + kb*8 + tig + 4];
            }
#pragma unroll
            for (int nf = 0; nf < 8; nf++) {
                unsigned b0 = Vtw[(nf*8+grp)*VSW + kb*8 + tig];
                unsigned b1 = Vtw[(nf*8+grp)*VSW + kb*8 + tig + 4];
#pragma unroll
                for (int mf = 0; mf < 2; mf++) {
                    float* c0 = &oacc[mf][nf][0];
                    asm volatile(
                        "mma.sync.aligned.m16n8k16.row.col.f32.f16.f16.f32 "
                        "{%0,%1,%2,%3}, {%4,%5,%6,%7}, {%8,%9}, {%0,%1,%2,%3};"
                        : "+f"(c0[0]), "+f"(c0[1]), "+f"(c0[2]), "+f"(c0[3])
                        : "r"(a[mf][0]), "r"(a[mf][1]), "r"(a[mf][2]), "r"(a[mf][3]),
                          "r"(b0), "r"(b1));
                }
            }
        }
    }

    // ---- epilogue: O / l, stored as half2 for the fp16 wo GEMM
#pragma unroll
    for (int mf = 0; mf < 2; mf++) {
        const float inv0 = 1.f / l[mf*2];
        const float inv1 = 1.f / l[mf*2+1];
        unsigned* o0 = O + (((size_t)(b*S_ + rb + mf*16 + grp    )*NH + h) << 5) + tig;
        unsigned* o1 = O + (((size_t)(b*S_ + rb + mf*16 + grp + 8)*NH + h) << 5) + tig;
#pragma unroll
        for (int nf = 0; nf < 8; nf++) {
            o0[nf*4] = pack_h2(oacc[mf][nf][0]*inv0, oacc[mf][nf][1]*inv0);
            o1[nf*4] = pack_h2(oacc[mf][nf][2]*inv1, oacc[mf][nf][3]*inv1);
        }
    }
}

// ---------------------------------------------------------------------------
extern "C" void kernel_launch(void* const* d_in, const int* in_sizes, int n_in,
                              void* d_out, int out_size)
{
    const float* x    = (const float*)d_in[0];
    const float* cosT = (const float*)d_in[1];
    const float* sinT = (const float*)d_in[2];
    const float* wq   = (const float*)d_in[3];
    const float* wk   = (const float*)d_in[4];
    const float* wv   = (const float*)d_in[5];
    const float* wo   = (const float*)d_in[6];
    float* out = (float*)d_out;

    float *Q, *K, *V;
    unsigned *Aat, *X, *Wq, *Wk, *Wv, *Wo;
    cudaGetSymbolAddress((void**)&Q,   g_Q);
    cudaGetSymbolAddress((void**)&K,   g_K);
    cudaGetSymbolAddress((void**)&V,   g_V);
    cudaGetSymbolAddress((void**)&Aat, g_A);
    cudaGetSymbolAddress((void**)&X,   g_X);
    cudaGetSymbolAddress((void**)&Wq,  g_Wq);
    cudaGetSymbolAddress((void**)&Wk,  g_Wk);
    cudaGetSymbolAddress((void**)&Wv,  g_Wv);
    cudaGetSymbolAddress((void**)&Wo,  g_Wo);

    static bool attr_set = false;
    if (!attr_set) {
        cudaFuncSetAttribute(hgemm, cudaFuncAttributeMaxDynamicSharedMemorySize, GEMM_SMEM);
        cudaFuncSetAttribute(flash_attn_fp16, cudaFuncAttributeMaxDynamicSharedMemorySize, FA_SMEM);
        attr_set = true;
    }

    // One-shot fp16 conversion of x + weights
    conv_fp16<<<CONV_BLOCKS, 256>>>(x, wq, wk, wv, wo, X, Wq, Wk, Wv, Wo);

    // Q projection (rope fused) -- 256 CTAs
    hgemm<<<dim3(HID/128, MROWS/128), 256, GEMM_SMEM>>>(
        X, Wq, Q, HID/128, 1, nullptr, nullptr, 0,
        MROWS, HID, HID, cosT, sinT);

    // K (rope) + V projections merged -- 128 CTAs
    hgemm<<<dim3(2*(NKV*HD)/128, MROWS/128), 256, GEMM_SMEM>>>(
        X, Wk, K, (NKV*HD)/128, 1, Wv, V, 0,
        MROWS, NKV*HD, HID, cosT, sinT);

    // fp16 tensor-core causal GQA flash attention
    flash_attn_fp16<<<dim3(NH, S_/128, B_), 128, FA_SMEM>>>(Q, K, V, Aat);

    // Output projection (Aat is half2 from the flash epilogue)
    hgemm<<<dim3(HID/128, MROWS/128), 256, GEMM_SMEM>>>(
        Aat, Wo, out, HID/128, 0, nullptr, nullptr, 0,
        MROWS, HID, HID, cosT, sinT);
}

// round 15
// speedup vs baseline: 1.9550x; 1.0449x over previous
#include <cuda_runtime.h>
#include <cuda_fp16.h>
#include <math.h>

#define B_  2
#define S_  2048
#define HID 1024
#define NH  16
#define NKV 4
#define HD  64
#define MROWS (B_*S_)   // 4096

// Scratch (no cudaMalloc allowed) -- Q/K/V/A are half2 words now
__device__ unsigned g_Q[MROWS * HID / 2];       // [B,S,NH,HD] half, pre-scaled 1/8
__device__ unsigned g_K[MROWS * NKV * HD / 2];  // half
__device__ unsigned g_V[MROWS * NKV * HD / 2];  // half
__device__ unsigned g_A[MROWS * HID / 2];       // attention out, half
// fp16 pre-converted inputs (half2 words)
__device__ unsigned g_X [MROWS * HID / 2];
__device__ unsigned g_Wq[HID * HID / 2];
__device__ unsigned g_Wk[NKV * HD * HID / 2];
__device__ unsigned g_Wv[NKV * HD * HID / 2];
__device__ unsigned g_Wo[HID * HID / 2];

__device__ __forceinline__ unsigned pack_h2(float a, float b) {
    __half2 h = __floats2half2_rn(a, b);
    return *(unsigned*)&h;
}

__device__ __forceinline__ unsigned prmt(unsigned a, unsigned b, unsigned sel) {
    unsigned d;
    asm("prmt.b32 %0, %1, %2, %3;" : "=r"(d) : "r"(a), "r"(b), "r"(sel));
    return d;
}

__device__ __forceinline__ unsigned smem_u32(const void* p) {
    unsigned a;
    asm("{ .reg .u64 t; cvta.to.shared.u64 t, %1; cvt.u32.u64 %0, t; }"
        : "=r"(a) : "l"(p));
    return a;
}

// ---------------------------------------------------------------------------
// One-shot fp16 conversion of x and weights (R14, measured).
// ---------------------------------------------------------------------------
__global__ void conv_fp16(const float* __restrict__ x,  const float* __restrict__ wq,
                          const float* __restrict__ wk, const float* __restrict__ wv,
                          const float* __restrict__ wo,
                          unsigned* __restrict__ X,  unsigned* __restrict__ Wq,
                          unsigned* __restrict__ Wk, unsigned* __restrict__ Wv,
                          unsigned* __restrict__ Wo)
{
    int blk = blockIdx.x;
    const float* src; unsigned* dst; int base;
    if      (blk < 4096) { src = x;  dst = X;  base = blk; }
    else if (blk < 5120) { src = wq; dst = Wq; base = blk - 4096; }
    else if (blk < 5376) { src = wk; dst = Wk; base = blk - 5120; }
    else if (blk < 5632) { src = wv; dst = Wv; base = blk - 5376; }
    else                 { src = wo; dst = Wo; base = blk - 5632; }
    int idx = base * 1024 + threadIdx.x * 4;
    float4 v = *(const float4*)(src + idx);
    *(uint2*)(dst + (idx >> 1)) = make_uint2(pack_h2(v.x, v.y), pack_h2(v.z, v.w));
}
#define CONV_BLOCKS (4096 + 1024 + 256 + 256 + 1024)

// ---------------------------------------------------------------------------
// fp16 tensor-core GEMM (mma.sync m16n8k16, fp32 accum) -- R14 body (measured)
// with a mode-controlled epilogue:
//   mode bit0: fused RoPE  | bit1: half2 output | bit2: pre-scale by 1/8
//   Q proj: 7 (rope+half+scale), K proj: 3 (rope+half), V proj: 2 (half),
//   wo proj: 0 (fp32 float2 output).
// ---------------------------------------------------------------------------
#define HST 20
#define GEMM_SMEM (2 * 2 * 128 * HST * 4)   // 40960 B dynamic

__global__ __launch_bounds__(256) void hgemm(
    const unsigned* __restrict__ A,
    const unsigned* __restrict__ W1, void* __restrict__ C1, int nx1, int mode1,
    const unsigned* __restrict__ W2, void* __restrict__ C2, int mode2,
    int M, int N, int K,
    const float* __restrict__ cosT, const float* __restrict__ sinT)
{
    extern __shared__ unsigned gsm[];
    unsigned* As = gsm;
    unsigned* Bs = gsm + 2*128*HST;

    int bx = blockIdx.x;
    const unsigned* W; void* C; int mode;
    if (bx < nx1) { W = W1; C = C1; mode = mode1; }
    else          { W = W2; C = C2; mode = mode2; bx -= nx1; }

    const int t    = threadIdx.x;
    const int wid  = t >> 5;
    const int lane = t & 31;
    const int grp  = lane >> 2;
    const int tig  = lane & 3;
    const int wm   = (wid >> 1) * 32;
    const int wn   = (wid & 1) * 64;

    const int lr  = t >> 2;
    const int lcs = (t & 3) * 4;

    const int K2 = K >> 1;
    const unsigned* Ab = A + (size_t)(blockIdx.y * 128) * K2;
    const unsigned* Wb = W + (size_t)(bx * 128) * K2;

    const unsigned sa = smem_u32(As);
    const unsigned sb = smem_u32(Bs);

    float acc[2][8][4];
#pragma unroll
    for (int mf = 0; mf < 2; mf++)
#pragma unroll
        for (int nf = 0; nf < 8; nf++) {
            acc[mf][nf][0]=0.f; acc[mf][nf][1]=0.f;
            acc[mf][nf][2]=0.f; acc[mf][nf][3]=0.f;
        }

#pragma unroll
    for (int i = 0; i < 2; i++) {
        int r = lr + i*64;
        unsigned da = sa + (unsigned)(r*HST + lcs) * 4u;
        unsigned db = sb + (unsigned)(r*HST + lcs) * 4u;
        asm volatile("cp.async.cg.shared.global [%0], [%1], 16;"
                     :: "r"(da), "l"(Ab + (size_t)r * K2 + lcs) : "memory");
        asm volatile("cp.async.cg.shared.global [%0], [%1], 16;"
                     :: "r"(db), "l"(Wb + (size_t)r * K2 + lcs) : "memory");
    }
    asm volatile("cp.async.commit_group;" ::: "memory");

    int buf = 0;
    for (int k0 = 0; k0 < K; k0 += 32) {
        const bool more = (k0 + 32 < K);
        asm volatile("cp.async.wait_group 0;" ::: "memory");
        __syncthreads();

        if (more) {
            const unsigned nb = (unsigned)((buf^1) * 128*HST) * 4u;
            const int kw = (k0 + 32) >> 1;
#pragma unroll
            for (int i = 0; i < 2; i++) {
                int r = lr + i*64;
                unsigned da = sa + nb + (unsigned)(r*HST + lcs) * 4u;
                unsigned db = sb + nb + (unsigned)(r*HST + lcs) * 4u;
                asm volatile("cp.async.cg.shared.global [%0], [%1], 16;"
                             :: "r"(da), "l"(Ab + (size_t)r * K2 + kw + lcs) : "memory");
                asm volatile("cp.async.cg.shared.global [%0], [%1], 16;"
                             :: "r"(db), "l"(Wb + (size_t)r * K2 + kw + lcs) : "memory");
            }
            asm volatile("cp.async.commit_group;" ::: "memory");
        }

        const unsigned* Ac = As + buf*128*HST;
        const unsigned* Bc = Bs + buf*128*HST;
#pragma unroll
        for (int c = 0; c < 2; c++) {
            const int kb = c * 8;
            unsigned af[2][4];
#pragma unroll
            for (int mf = 0; mf < 2; mf++) {
                int mrow = wm + mf*16 + grp;
                af[mf][0] = Ac[(mrow  )*HST + kb + tig];
                af[mf][1] = Ac[(mrow+8)*HST + kb + tig];
                af[mf][2] = Ac[(mrow  )*HST + kb + tig + 4];
                af[mf][3] = Ac[(mrow+8)*HST + kb + tig + 4];
            }
#pragma unroll
            for (int nf = 0; nf < 8; nf++) {
                int n = wn + nf*8 + grp;
                unsigned b0 = Bc[n*HST + kb + tig];
                unsigned b1 = Bc[n*HST + kb + tig + 4];
#pragma unroll
                for (int mf = 0; mf < 2; mf++) {
                    float* c0 = &acc[mf][nf][0];
                    asm volatile(
                        "mma.sync.aligned.m16n8k16.row.col.f32.f16.f16.f32 "
                        "{%0,%1,%2,%3}, {%4,%5,%6,%7}, {%8,%9}, {%0,%1,%2,%3};"
                        : "+f"(c0[0]), "+f"(c0[1]), "+f"(c0[2]), "+f"(c0[3])
                        : "r"(af[mf][0]), "r"(af[mf][1]), "r"(af[mf][2]), "r"(af[mf][3]),
                          "r"(b0), "r"(b1));
                }
            }
        }
        buf ^= 1;
    }

    if (mode & 1) {   // fused RoPE
#pragma unroll
        for (int mf = 0; mf < 2; mf++) {
#pragma unroll
            for (int nf = 0; nf < 4; nf++) {
                const int i0 = nf*8 + tig*2;
#pragma unroll
                for (int hh = 0; hh < 2; hh++) {
                    int row = blockIdx.y*128 + wm + mf*16 + grp + hh*8;
                    int s   = row & (S_ - 1);
#pragma unroll
                    for (int j = 0; j < 2; j++) {
                        float c  = cosT[s*HD + i0 + j];
                        float sn = sinT[s*HD + i0 + j];
                        float L = acc[mf][nf  ][hh*2 + j];
                        float H = acc[mf][nf+4][hh*2 + j];
                        acc[mf][nf  ][hh*2 + j] = L*c - H*sn;
                        acc[mf][nf+4][hh*2 + j] = H*c + L*sn;
                    }
                }
            }
        }
    }

    const float osc = (mode & 4) ? 0.125f : 1.0f;
    if (mode & 2) {   // half2 output
        unsigned* Ch = (unsigned*)C;
        const int Nw = N >> 1;
#pragma unroll
        for (int mf = 0; mf < 2; mf++) {
#pragma unroll
            for (int nf = 0; nf < 8; nf++) {
                float* c0 = &acc[mf][nf][0];
                int row  = blockIdx.y*128 + wm + mf*16 + grp;
                int colw = (bx*128 + wn + nf*8 + tig*2) >> 1;
                Ch[(size_t)row*Nw + colw]     = pack_h2(c0[0]*osc, c0[1]*osc);
                Ch[(size_t)(row+8)*Nw + colw] = pack_h2(c0[2]*osc, c0[3]*osc);
            }
        }
    } else {          // fp32 output
        float* Cf = (float*)C;
#pragma unroll
        for (int mf = 0; mf < 2; mf++) {
#pragma unroll
            for (int nf = 0; nf < 8; nf++) {
                float* c0 = &acc[mf][nf][0];
                int row = blockIdx.y*128 + wm + mf*16 + grp;
                int col = bx*128 + wn + nf*8 + tig*2;
                *(float2*)(Cf + (size_t)row*N + col)     = make_float2(c0[0], c0[1]);
                *(float2*)(Cf + (size_t)(row+8)*N + col) = make_float2(c0[2], c0[3]);
            }
        }
    }
}

// ---------------------------------------------------------------------------
// fp16 flash attention, lean loader edition:
//  - Q/K/V arrive as half2 (Q pre-scaled by 1/8 at the GEMM)
//  - Q frags: plain 32-bit word loads
//  - K tile: pure cp.async 16B copies (no staging, no converts)
//  - V tile: transpose via 2x LDG.32 + 2x PRMT per output pair
// ---------------------------------------------------------------------------
#define KSW 36
#define VSW 36
#define PSW 36
#define FA_SMEM ((64*KSW + 64*VSW + 128*PSW) * 4)   // 36864 B

__global__ __launch_bounds__(128) void flash_attn_fp16(
    const unsigned* __restrict__ Qh, const unsigned* __restrict__ Kh,
    const unsigned* __restrict__ Vh, unsigned* __restrict__ O)
{
    extern __shared__ unsigned fsm[];
    unsigned* Ksw = fsm;               // [64][KSW]  half2, [key][dim]
    unsigned* Vtw = Ksw + 64*KSW;      // [64][VSW]  half2, [dim][key]
    unsigned* Psw = Vtw + 64*VSW;      // [128][PSW] half2, [row][key]

    const int h  = blockIdx.x;
    const int bm = (gridDim.y - 1) - blockIdx.y;
    const int b  = blockIdx.z;
    const int hk = h >> 2;
    const int t    = threadIdx.x;
    const int w    = t >> 5;
    const int lane = t & 31;
    const int grp  = lane >> 2;
    const int tig  = lane & 3;
    const int rb   = bm*128 + w*32;

    const unsigned ksw_base = smem_u32(Ksw);

    // ---- Q fragments: direct half2-word loads (pre-scaled at the GEMM)
    unsigned qf[2][4][4];
#pragma unroll
    for (int mf = 0; mf < 2; mf++) {
        const unsigned* q0 = Qh + (((size_t)(b*S_ + rb + mf*16 + grp    )*NH + h) << 5);
        const unsigned* q1 = Qh + (((size_t)(b*S_ + rb + mf*16 + grp + 8)*NH + h) << 5);
#pragma unroll
        for (int c = 0; c < 4; c++) {
            qf[mf][c][0] = q0[c*8 + tig];
            qf[mf][c][1] = q1[c*8 + tig];
            qf[mf][c][2] = q0[c*8 + tig + 4];
            qf[mf][c][3] = q1[c*8 + tig + 4];
        }
    }

    float oacc[2][8][4];
#pragma unroll
    for (int mf = 0; mf < 2; mf++)
#pragma unroll
        for (int nf = 0; nf < 8; nf++) {
            oacc[mf][nf][0]=0.f; oacc[mf][nf][1]=0.f;
            oacc[mf][nf][2]=0.f; oacc[mf][nf][3]=0.f;
        }
    float m[4]  = {-1e30f, -1e30f, -1e30f, -1e30f};
    float l[4]  = {0.f, 0.f, 0.f, 0.f};

    const int ntiles = 2*(bm + 1);
    for (int tile = 0; tile < ntiles; tile++) {
        __syncthreads();   // prev tile's K/V reads done
        // ---- K tile via cp.async: 64 rows x 32 words, 16B chunks
#pragma unroll
        for (int i = 0; i < 4; i++) {
            int chunk = t + i*128;           // 0..511
            int r  = chunk >> 3;
            int cw = (chunk & 7) * 4;
            unsigned dst = ksw_base + (unsigned)(r*KSW + cw) * 4u;
            const unsigned* src = Kh + (((size_t)(b*S_ + tile*64 + r)*NKV + hk) << 5) + cw;
            asm volatile("cp.async.ca.shared.global [%0], [%1], 16;"
                         :: "r"(dst), "l"(src) : "memory");
        }
        asm volatile("cp.async.commit_group;" ::: "memory");

        // ---- V tile transposed: 2x LDG.32 + 2x PRMT per half2 pair
#pragma unroll
        for (int i = 0; i < 8; i++) {
            int lin = t + i*128;             // 0..1023
            int kp  = lin >> 5;              // key pair 0..31
            int d2  = lin & 31;              // dim word 0..31
            size_t gb = (((size_t)(b*S_ + tile*64 + 2*kp)*NKV + hk) << 5) + d2;
            unsigned va = Vh[gb];                    // (V[2kp][2d2], V[2kp][2d2+1])
            unsigned vb = Vh[gb + (NKV << 5)];       // (V[2kp+1][2d2], ...)
            Vtw[(2*d2  )*VSW + kp] = prmt(va, vb, 0x5410);
            Vtw[(2*d2+1)*VSW + kp] = prmt(va, vb, 0x7632);
        }
        asm volatile("cp.async.wait_group 0;" ::: "memory");
        __syncthreads();

        // ---- S = Q K^T (Q already scaled)
        float sacc[2][8][4];
#pragma unroll
        for (int mf = 0; mf < 2; mf++)
#pragma unroll
            for (int nf = 0; nf < 8; nf++) {
                sacc[mf][nf][0]=0.f; sacc[mf][nf][1]=0.f;
                sacc[mf][nf][2]=0.f; sacc[mf][nf][3]=0.f;
            }
#pragma unroll
        for (int c = 0; c < 4; c++) {
#pragma unroll
            for (int nf = 0; nf < 8; nf++) {
                unsigned b0 = Ksw[(nf*8+grp)*KSW + c*8 + tig];
                unsigned b1 = Ksw[(nf*8+grp)*KSW + c*8 + tig + 4];
#pragma unroll
                for (int mf = 0; mf < 2; mf++) {
                    float* c0 = &sacc[mf][nf][0];
                    asm volatile(
                        "mma.sync.aligned.m16n8k16.row.col.f32.f16.f16.f32 "
                        "{%0,%1,%2,%3}, {%4,%5,%6,%7}, {%8,%9}, {%0,%1,%2,%3};"
                        : "+f"(c0[0]), "+f"(c0[1]), "+f"(c0[2]), "+f"(c0[3])
                        : "r"(qf[mf][c][0]), "r"(qf[mf][c][1]),
                          "r"(qf[mf][c][2]), "r"(qf[mf][c][3]),
                          "r"(b0), "r"(b1));
                }
            }
        }

        // ---- online softmax
        const bool diag = (tile >= 2*bm);
        const int colb = tile*64;
#pragma unroll
        for (int mf = 0; mf < 2; mf++) {
            const int r0 = rb + mf*16 + grp;
            const int r1 = r0 + 8;
            float mt0 = -1e30f, mt1 = -1e30f;
#pragma unroll
            for (int nf = 0; nf < 8; nf++) {
                const int c0i = colb + nf*8 + tig*2;
                if (diag) {
                    if (c0i     > r0) sacc[mf][nf][0] = -1e30f;
                    if (c0i + 1 > r0) sacc[mf][nf][1] = -1e30f;
                    if (c0i     > r1) sacc[mf][nf][2] = -1e30f;
                    if (c0i + 1 > r1) sacc[mf][nf][3] = -1e30f;
                }
                mt0 = fmaxf(mt0, fmaxf(sacc[mf][nf][0], sacc[mf][nf][1]));
                mt1 = fmaxf(mt1, fmaxf(sacc[mf][nf][2], sacc[mf][nf][3]));
            }
            mt0 = fmaxf(mt0, __shfl_xor_sync(0xffffffffu, mt0, 1));
            mt0 = fmaxf(mt0, __shfl_xor_sync(0xffffffffu, mt0, 2));
            mt1 = fmaxf(mt1, __shfl_xor_sync(0xffffffffu, mt1, 1));
            mt1 = fmaxf(mt1, __shfl_xor_sync(0xffffffffu, mt1, 2));

            const float mn0 = fmaxf(m[mf*2  ], mt0);
            const float mn1 = fmaxf(m[mf*2+1], mt1);
            const float cr0 = __expf(m[mf*2  ] - mn0);
            const float cr1 = __expf(m[mf*2+1] - mn1);
            float ps0 = 0.f, ps1 = 0.f;

            unsigned* P0 = &Psw[(w*32 + mf*16 + grp)*PSW + tig];
            unsigned* P1 = P0 + 8*PSW;
#pragma unroll
            for (int nf = 0; nf < 8; nf++) {
                float p00 = __expf(sacc[mf][nf][0] - mn0);
                float p01 = __expf(sacc[mf][nf][1] - mn0);
                float p10 = __expf(sacc[mf][nf][2] - mn1);
                float p11 = __expf(sacc[mf][nf][3] - mn1);
                ps0 += p00 + p01;
                ps1 += p10 + p11;
                P0[nf*4] = pack_h2(p00, p01);
                P1[nf*4] = pack_h2(p10, p11);
            }
            ps0 += __shfl_xor_sync(0xffffffffu, ps0, 1);
            ps0 += __shfl_xor_sync(0xffffffffu, ps0, 2);
            ps1 += __shfl_xor_sync(0xffffffffu, ps1, 1);
            ps1 += __shfl_xor_sync(0xffffffffu, ps1, 2);
            l[mf*2  ] = l[mf*2  ]*cr0 + ps0;  m[mf*2  ] = mn0;
            l[mf*2+1] = l[mf*2+1]*cr1 + ps1;  m[mf*2+1] = mn1;
#pragma unroll
            for (int nf = 0; nf < 8; nf++) {
                oacc[mf][nf][0] *= cr0; oacc[mf][nf][1] *= cr0;
                oacc[mf][nf][2] *= cr1; oacc[mf][nf][3] *= cr1;
            }
        }
        __syncwarp();

        // ---- O += P V
#pragma unroll
        for (int kb = 0; kb < 4; kb++) {
            unsigned a[2][4];
#pragma unroll
            for (int mf = 0; mf < 2; mf++) {
                const int pr = w*32 + mf*16 + grp;
                a[mf][0] = Psw[(pr    )*PSW + kb*8 + tig];
                a[mf][1] = Psw[(pr + 8)*PSW + kb*8 + tig];
                a[mf][2] = Psw[(pr    )*PSW + kb*8 + tig + 4];
                a[mf][3] = Psw[(pr + 8)*PSW + kb*8 + tig + 4];
            }
#pragma unroll
            for (int nf = 0; nf < 8; nf++) {
                unsigned b0 = Vtw[(nf*8+grp)*VSW + kb*8 + tig];
                unsigned b1 = Vtw[(nf*8+grp)*VSW + kb*8 + tig + 4];
#pragma unroll
                for (int mf = 0; mf < 2; mf++) {
                    float* c0 = &oacc[mf][nf][0];
                    asm volatile(
                        "mma.sync.aligned.m16n8k16.row.col.f32.f16.f16.f32 "
                        "{%0,%1,%2,%3}, {%4,%5,%6,%7}, {%8,%9}, {%0,%1,%2,%3};"
                        : "+f"(c0[0]), "+f"(c0[1]), "+f"(c0[2]), "+f"(c0[3])
                        : "r"(a[mf][0]), "r"(a[mf][1]), "r"(a[mf][2]), "r"(a[mf][3]),
                          "r"(b0), "r"(b1));
                }
            }
        }
    }

    // ---- epilogue: O / l as half2
#pragma unroll
    for (int mf = 0; mf < 2; mf++) {
        const float inv0 = 1.f / l[mf*2];
        const float inv1 = 1.f / l[mf*2+1];
        unsigned* o0 = O + (((size_t)(b*S_ + rb + mf*16 + grp    )*NH + h) << 5) + tig;
        unsigned* o1 = O + (((size_t)(b*S_ + rb + mf*16 + grp + 8)*NH + h) << 5) + tig;
#pragma unroll
        for (int nf = 0; nf < 8; nf++) {
            o0[nf*4] = pack_h2(oacc[mf][nf][0]*inv0, oacc[mf][nf][1]*inv0);
            o1[nf*4] = pack_h2(oacc[mf][nf][2]*inv1, oacc[mf][nf][3]*inv1);
        }
    }
}

// ---------------------------------------------------------------------------
extern "C" void kernel_launch(void* const* d_in, const int* in_sizes, int n_in,
                              void* d_out, int out_size)
{
    const float* x    = (const float*)d_in[0];
    const float* cosT = (const float*)d_in[1];
    const float* sinT = (const float*)d_in[2];
    const float* wq   = (const float*)d_in[3];
    const float* wk   = (const float*)d_in[4];
    const float* wv   = (const float*)d_in[5];
    const float* wo   = (const float*)d_in[6];
    float* out = (float*)d_out;

    unsigned *Q, *K, *V, *Aat, *X, *Wq, *Wk, *Wv, *Wo;
    cudaGetSymbolAddress((void**)&Q,   g_Q);
    cudaGetSymbolAddress((void**)&K,   g_K);
    cudaGetSymbolAddress((void**)&V,   g_V);
    cudaGetSymbolAddress((void**)&Aat, g_A);
    cudaGetSymbolAddress((void**)&X,   g_X);
    cudaGetSymbolAddress((void**)&Wq,  g_Wq);
    cudaGetSymbolAddress((void**)&Wk,  g_Wk);
    cudaGetSymbolAddress((void**)&Wv,  g_Wv);
    cudaGetSymbolAddress((void**)&Wo,  g_Wo);

    static bool attr_set = false;
    if (!attr_set) {
        cudaFuncSetAttribute(hgemm, cudaFuncAttributeMaxDynamicSharedMemorySize, GEMM_SMEM);
        cudaFuncSetAttribute(flash_attn_fp16, cudaFuncAttributeMaxDynamicSharedMemorySize, FA_SMEM);
        attr_set = true;
    }

    // One-shot fp16 conversion of x + weights
    conv_fp16<<<CONV_BLOCKS, 256>>>(x, wq, wk, wv, wo, X, Wq, Wk, Wv, Wo);

    // Q projection: rope + half out + 1/8 scale (mode 7)
    hgemm<<<dim3(HID/128, MROWS/128), 256, GEMM_SMEM>>>(
        X, Wq, Q, HID/128, 7, nullptr, nullptr, 0,
        MROWS, HID, HID, cosT, sinT);

    // K (rope+half, mode 3) + V (half, mode 2) merged
    hgemm<<<dim3(2*(NKV*HD)/128, MROWS/128), 256, GEMM_SMEM>>>(
        X, Wk, K, (NKV*HD)/128, 3, Wv, V, 2,
        MROWS, NKV*HD, HID, cosT, sinT);

    // fp16 flash attention (lean loaders)
    flash_attn_fp16<<<dim3(NH, S_/128, B_), 128, FA_SMEM>>>(Q, K, V, Aat);

    // Output projection: fp32 out (mode 0)
    hgemm<<<dim3(HID/128, MROWS/128), 256, GEMM_SMEM>>>(
        Aat, Wo, out, HID/128, 0, nullptr, nullptr, 0,
        MROWS, HID, HID, cosT, sinT);
}

// round 17
// speedup vs baseline: 1.9558x; 1.0004x over previous
#include <cuda_runtime.h>
#include <cuda_fp16.h>
#include <math.h>

#define B_  2
#define S_  2048
#define HID 1024
#define NH  16
#define NKV 4
#define HD  64
#define MROWS (B_*S_)   // 4096

// Scratch (no cudaMalloc allowed) -- Q/K/V/A are half2 words
__device__ unsigned g_Q[MROWS * HID / 2];       // [B,S,NH,HD] half, pre-scaled 1/8
__device__ unsigned g_K[MROWS * NKV * HD / 2];  // half
__device__ unsigned g_V[MROWS * NKV * HD / 2];  // half
__device__ unsigned g_A[MROWS * HID / 2];       // attention out, half
// fp16 pre-converted inputs (half2 words)
__device__ unsigned g_X [MROWS * HID / 2];
__device__ unsigned g_Wq[HID * HID / 2];
__device__ unsigned g_Wk[NKV * HD * HID / 2];
__device__ unsigned g_Wv[NKV * HD * HID / 2];
__device__ unsigned g_Wo[HID * HID / 2];

__device__ __forceinline__ unsigned pack_h2(float a, float b) {
    __half2 h = __floats2half2_rn(a, b);
    return *(unsigned*)&h;
}

__device__ __forceinline__ unsigned prmt(unsigned a, unsigned b, unsigned sel) {
    unsigned d;
    asm("prmt.b32 %0, %1, %2, %3;" : "=r"(d) : "r"(a), "r"(b), "r"(sel));
    return d;
}

__device__ __forceinline__ unsigned smem_u32(const void* p) {
    unsigned a;
    asm("{ .reg .u64 t; cvta.to.shared.u64 t, %1; cvt.u32.u64 %0, t; }"
        : "=r"(a) : "l"(p));
    return a;
}

// ---------------------------------------------------------------------------
// One-shot fp16 conversion of x and weights (measured).
// ---------------------------------------------------------------------------
__global__ void conv_fp16(const float* __restrict__ x,  const float* __restrict__ wq,
                          const float* __restrict__ wk, const float* __restrict__ wv,
                          const float* __restrict__ wo,
                          unsigned* __restrict__ X,  unsigned* __restrict__ Wq,
                          unsigned* __restrict__ Wk, unsigned* __restrict__ Wv,
                          unsigned* __restrict__ Wo)
{
    int blk = blockIdx.x;
    const float* src; unsigned* dst; int base;
    if      (blk < 4096) { src = x;  dst = X;  base = blk; }
    else if (blk < 5120) { src = wq; dst = Wq; base = blk - 4096; }
    else if (blk < 5376) { src = wk; dst = Wk; base = blk - 5120; }
    else if (blk < 5632) { src = wv; dst = Wv; base = blk - 5376; }
    else                 { src = wo; dst = Wo; base = blk - 5632; }
    int idx = base * 1024 + threadIdx.x * 4;
    float4 v = *(const float4*)(src + idx);
    *(uint2*)(dst + (idx >> 1)) = make_uint2(pack_h2(v.x, v.y), pack_h2(v.z, v.w));
}
#define CONV_BLOCKS (4096 + 1024 + 256 + 256 + 1024)

// ---------------------------------------------------------------------------
// fp16 tensor-core GEMM (mma.sync m16n8k16, fp32 accum) -- R15 (measured).
// mode bit0: fused RoPE | bit1: half2 output | bit2: pre-scale by 1/8
// ---------------------------------------------------------------------------
#define HST 20
#define GEMM_SMEM (2 * 2 * 128 * HST * 4)   // 40960 B dynamic

__global__ __launch_bounds__(256) void hgemm(
    const unsigned* __restrict__ A,
    const unsigned* __restrict__ W1, void* __restrict__ C1, int nx1, int mode1,
    const unsigned* __restrict__ W2, void* __restrict__ C2, int mode2,
    int M, int N, int K,
    const float* __restrict__ cosT, const float* __restrict__ sinT)
{
    extern __shared__ unsigned gsm[];
    unsigned* As = gsm;
    unsigned* Bs = gsm + 2*128*HST;

    int bx = blockIdx.x;
    const unsigned* W; void* C; int mode;
    if (bx < nx1) { W = W1; C = C1; mode = mode1; }
    else          { W = W2; C = C2; mode = mode2; bx -= nx1; }

    const int t    = threadIdx.x;
    const int wid  = t >> 5;
    const int lane = t & 31;
    const int grp  = lane >> 2;
    const int tig  = lane & 3;
    const int wm   = (wid >> 1) * 32;
    const int wn   = (wid & 1) * 64;

    const int lr  = t >> 2;
    const int lcs = (t & 3) * 4;

    const int K2 = K >> 1;
    const unsigned* Ab = A + (size_t)(blockIdx.y * 128) * K2;
    const unsigned* Wb = W + (size_t)(bx * 128) * K2;

    const unsigned sa = smem_u32(As);
    const unsigned sb = smem_u32(Bs);

    float acc[2][8][4];
#pragma unroll
    for (int mf = 0; mf < 2; mf++)
#pragma unroll
        for (int nf = 0; nf < 8; nf++) {
            acc[mf][nf][0]=0.f; acc[mf][nf][1]=0.f;
            acc[mf][nf][2]=0.f; acc[mf][nf][3]=0.f;
        }

#pragma unroll
    for (int i = 0; i < 2; i++) {
        int r = lr + i*64;
        unsigned da = sa + (unsigned)(r*HST + lcs) * 4u;
        unsigned db = sb + (unsigned)(r*HST + lcs) * 4u;
        asm volatile("cp.async.cg.shared.global [%0], [%1], 16;"
                     :: "r"(da), "l"(Ab + (size_t)r * K2 + lcs) : "memory");
        asm volatile("cp.async.cg.shared.global [%0], [%1], 16;"
                     :: "r"(db), "l"(Wb + (size_t)r * K2 + lcs) : "memory");
    }
    asm volatile("cp.async.commit_group;" ::: "memory");

    int buf = 0;
    for (int k0 = 0; k0 < K; k0 += 32) {
        const bool more = (k0 + 32 < K);
        asm volatile("cp.async.wait_group 0;" ::: "memory");
        __syncthreads();

        if (more) {
            const unsigned nb = (unsigned)((buf^1) * 128*HST) * 4u;
            const int kw = (k0 + 32) >> 1;
#pragma unroll
            for (int i = 0; i < 2; i++) {
                int r = lr + i*64;
                unsigned da = sa + nb + (unsigned)(r*HST + lcs) * 4u;
                unsigned db = sb + nb + (unsigned)(r*HST + lcs) * 4u;
                asm volatile("cp.async.cg.shared.global [%0], [%1], 16;"
                             :: "r"(da), "l"(Ab + (size_t)r * K2 + kw + lcs) : "memory");
                asm volatile("cp.async.cg.shared.global [%0], [%1], 16;"
                             :: "r"(db), "l"(Wb + (size_t)r * K2 + kw + lcs) : "memory");
            }
            asm volatile("cp.async.commit_group;" ::: "memory");
        }

        const unsigned* Ac = As + buf*128*HST;
        const unsigned* Bc = Bs + buf*128*HST;
#pragma unroll
        for (int c = 0; c < 2; c++) {
            const int kb = c * 8;
            unsigned af[2][4];
#pragma unroll
            for (int mf = 0; mf < 2; mf++) {
                int mrow = wm + mf*16 + grp;
                af[mf][0] = Ac[(mrow  )*HST + kb + tig];
                af[mf][1] = Ac[(mrow+8)*HST + kb + tig];
                af[mf][2] = Ac[(mrow  )*HST + kb + tig + 4];
                af[mf][3] = Ac[(mrow+8)*HST + kb + tig + 4];
            }
#pragma unroll
            for (int nf = 0; nf < 8; nf++) {
                int n = wn + nf*8 + grp;
                unsigned b0 = Bc[n*HST + kb + tig];
                unsigned b1 = Bc[n*HST + kb + tig + 4];
#pragma unroll
                for (int mf = 0; mf < 2; mf++) {
                    float* c0 = &acc[mf][nf][0];
                    asm volatile(
                        "mma.sync.aligned.m16n8k16.row.col.f32.f16.f16.f32 "
                        "{%0,%1,%2,%3}, {%4,%5,%6,%7}, {%8,%9}, {%0,%1,%2,%3};"
                        : "+f"(c0[0]), "+f"(c0[1]), "+f"(c0[2]), "+f"(c0[3])
                        : "r"(af[mf][0]), "r"(af[mf][1]), "r"(af[mf][2]), "r"(af[mf][3]),
                          "r"(b0), "r"(b1));
                }
            }
        }
        buf ^= 1;
    }

    if (mode & 1) {
#pragma unroll
        for (int mf = 0; mf < 2; mf++) {
#pragma unroll
            for (int nf = 0; nf < 4; nf++) {
                const int i0 = nf*8 + tig*2;
#pragma unroll
                for (int hh = 0; hh < 2; hh++) {
                    int row = blockIdx.y*128 + wm + mf*16 + grp + hh*8;
                    int s   = row & (S_ - 1);
#pragma unroll
                    for (int j = 0; j < 2; j++) {
                        float c  = cosT[s*HD + i0 + j];
                        float sn = sinT[s*HD + i0 + j];
                        float L = acc[mf][nf  ][hh*2 + j];
                        float H = acc[mf][nf+4][hh*2 + j];
                        acc[mf][nf  ][hh*2 + j] = L*c - H*sn;
                        acc[mf][nf+4][hh*2 + j] = H*c + L*sn;
                    }
                }
            }
        }
    }

    const float osc = (mode & 4) ? 0.125f : 1.0f;
    if (mode & 2) {
        unsigned* Ch = (unsigned*)C;
        const int Nw = N >> 1;
#pragma unroll
        for (int mf = 0; mf < 2; mf++) {
#pragma unroll
            for (int nf = 0; nf < 8; nf++) {
                float* c0 = &acc[mf][nf][0];
                int row  = blockIdx.y*128 + wm + mf*16 + grp;
                int colw = (bx*128 + wn + nf*8 + tig*2) >> 1;
                Ch[(size_t)row*Nw + colw]     = pack_h2(c0[0]*osc, c0[1]*osc);
                Ch[(size_t)(row+8)*Nw + colw] = pack_h2(c0[2]*osc, c0[3]*osc);
            }
        }
    } else {
        float* Cf = (float*)C;
#pragma unroll
        for (int mf = 0; mf < 2; mf++) {
#pragma unroll
            for (int nf = 0; nf < 8; nf++) {
                float* c0 = &acc[mf][nf][0];
                int row = blockIdx.y*128 + wm + mf*16 + grp;
                int col = bx*128 + wn + nf*8 + tig*2;
                *(float2*)(Cf + (size_t)row*N + col)     = make_float2(c0[0], c0[1]);
                *(float2*)(Cf + (size_t)(row+8)*N + col) = make_float2(c0[2], c0[3]);
            }
        }
    }
}

// ---------------------------------------------------------------------------
// fp16 flash attention v3b: double-buffered, software-pipelined K/V loads.
// R16 structure with the K-loader FIXED: 512 16B chunks per tile
// (i<4, chunk = t + i*128, r = chunk>>3, cw = (chunk&7)*4) -- the R15 mapping.
// ---------------------------------------------------------------------------
#define KSW 36
#define VSW 36
#define PSW 36
#define KVBUF (64*KSW + 64*VSW)                    // words per K/V buffer
#define FA_SMEM ((2*KVBUF + 128*PSW) * 4)          // 55296 B

__global__ __launch_bounds__(128) void flash_attn_fp16(
    const unsigned* __restrict__ Qh, const unsigned* __restrict__ Kh,
    const unsigned* __restrict__ Vh, unsigned* __restrict__ O)
{
    extern __shared__ unsigned fsm[];
    unsigned* Psw = fsm + 2*KVBUF;     // [128][PSW]

    const int h  = blockIdx.x;
    const int bm = (gridDim.y - 1) - blockIdx.y;   // heaviest blocks first
    const int b  = blockIdx.z;
    const int hk = h >> 2;
    const int t    = threadIdx.x;
    const int w    = t >> 5;
    const int lane = t & 31;
    const int grp  = lane >> 2;
    const int tig  = lane & 3;
    const int rb   = bm*128 + w*32;

    const unsigned smb = smem_u32(fsm);

    // V loader indices
    const int vkp = t >> 2;            // key pair 0..31
    const int vd0 = (t & 3) * 8;       // dim word base 0,8,16,24 (+i)

    // ---- Q fragments: direct half2-word loads (pre-scaled at the GEMM)
    unsigned qf[2][4][4];
#pragma unroll
    for (int mf = 0; mf < 2; mf++) {
        const unsigned* q0 = Qh + (((size_t)(b*S_ + rb + mf*16 + grp    )*NH + h) << 5);
        const unsigned* q1 = Qh + (((size_t)(b*S_ + rb + mf*16 + grp + 8)*NH + h) << 5);
#pragma unroll
        for (int c = 0; c < 4; c++) {
            qf[mf][c][0] = q0[c*8 + tig];
            qf[mf][c][1] = q1[c*8 + tig];
            qf[mf][c][2] = q0[c*8 + tig + 4];
            qf[mf][c][3] = q1[c*8 + tig + 4];
        }
    }

    float oacc[2][8][4];
#pragma unroll
    for (int mf = 0; mf < 2; mf++)
#pragma unroll
        for (int nf = 0; nf < 8; nf++) {
            oacc[mf][nf][0]=0.f; oacc[mf][nf][1]=0.f;
            oacc[mf][nf][2]=0.f; oacc[mf][nf][3]=0.f;
        }
    float m[4]  = {-1e30f, -1e30f, -1e30f, -1e30f};
    float l[4]  = {0.f, 0.f, 0.f, 0.f};

    const int ntiles = 2*(bm + 1);

    // ---- prologue: tile 0 into buffer 0 (K cp.async 512 chunks, V direct)
    {
#pragma unroll
        for (int i = 0; i < 4; i++) {
            int chunk = t + i*128;          // 0..511
            int r  = chunk >> 3;
            int cw = (chunk & 7) * 4;
            unsigned dst = smb + (unsigned)(r*KSW + cw) * 4u;
            const unsigned* src = Kh + (((size_t)(b*S_ + r)*NKV + hk) << 5) + cw;
            asm volatile("cp.async.ca.shared.global [%0], [%1], 16;"
                         :: "r"(dst), "l"(src) : "memory");
        }
        asm volatile("cp.async.commit_group;" ::: "memory");
        unsigned* Vt0 = fsm + 64*KSW;
#pragma unroll
        for (int i = 0; i < 8; i++) {
            int d2 = vd0 + i;
            size_t gb = (((size_t)(b*S_ + 2*vkp)*NKV + hk) << 5) + d2;
            unsigned va = Vh[gb];
            unsigned vb = Vh[gb + (NKV << 5)];
            Vt0[(2*d2  )*VSW + vkp] = prmt(va, vb, 0x5410);
            Vt0[(2*d2+1)*VSW + vkp] = prmt(va, vb, 0x7632);
        }
    }

    for (int tile = 0; tile < ntiles; tile++) {
        const int cur = tile & 1;
        const bool more = (tile + 1 < ntiles);

        __syncthreads();   // compute(t-1) done everywhere -> nxt buffer free

        // ---- issue K(t+1) cp.async + V(t+1) LDGs (staged in regs)
        unsigned va[8], vb[8];
        if (more) {
            const unsigned nxtb = smb + (unsigned)((cur^1) * KVBUF) * 4u;
#pragma unroll
            for (int i = 0; i < 4; i++) {
                int chunk = t + i*128;
                int r  = chunk >> 3;
                int cw = (chunk & 7) * 4;
                unsigned dst = nxtb + (unsigned)(r*KSW + cw) * 4u;
                const unsigned* src = Kh + (((size_t)(b*S_ + (tile+1)*64 + r)*NKV + hk) << 5) + cw;
                asm volatile("cp.async.ca.shared.global [%0], [%1], 16;"
                             :: "r"(dst), "l"(src) : "memory");
            }
            asm volatile("cp.async.commit_group;" ::: "memory");
#pragma unroll
            for (int i = 0; i < 8; i++) {
                size_t gb = (((size_t)(b*S_ + (tile+1)*64 + 2*vkp)*NKV + hk) << 5) + vd0 + i;
                va[i] = Vh[gb];
                vb[i] = Vh[gb + (NKV << 5)];
            }
            asm volatile("cp.async.wait_group 1;" ::: "memory");   // K(t) done
        } else {
            asm volatile("cp.async.wait_group 0;" ::: "memory");
        }
        __syncthreads();   // K(t) visible

        const unsigned* Ksw = fsm + cur * KVBUF;
        const unsigned* Vtw = Ksw + 64*KSW;

        // ---- S = Q K^T
        float sacc[2][8][4];
#pragma unroll
        for (int mf = 0; mf < 2; mf++)
#pragma unroll
            for (int nf = 0; nf < 8; nf++) {
                sacc[mf][nf][0]=0.f; sacc[mf][nf][1]=0.f;
                sacc[mf][nf][2]=0.f; sacc[mf][nf][3]=0.f;
            }
#pragma unroll
        for (int c = 0; c < 4; c++) {
#pragma unroll
            for (int nf = 0; nf < 8; nf++) {
                unsigned b0 = Ksw[(nf*8+grp)*KSW + c*8 + tig];
                unsigned b1 = Ksw[(nf*8+grp)*KSW + c*8 + tig + 4];
#pragma unroll
                for (int mf = 0; mf < 2; mf++) {
                    float* c0 = &sacc[mf][nf][0];
                    asm volatile(
                        "mma.sync.aligned.m16n8k16.row.col.f32.f16.f16.f32 "
                        "{%0,%1,%2,%3}, {%4,%5,%6,%7}, {%8,%9}, {%0,%1,%2,%3};"
                        : "+f"(c0[0]), "+f"(c0[1]), "+f"(c0[2]), "+f"(c0[3])
                        : "r"(qf[mf][c][0]), "r"(qf[mf][c][1]),
                          "r"(qf[mf][c][2]), "r"(qf[mf][c][3]),
                          "r"(b0), "r"(b1));
                }
            }
        }

        // ---- store V(t+1) into nxt buffer (LDG latency hidden behind QK)
        if (more) {
            unsigned* Vn = fsm + (cur^1) * KVBUF + 64*KSW;
#pragma unroll
            for (int i = 0; i < 8; i++) {
                int d2 = vd0 + i;
                Vn[(2*d2  )*VSW + vkp] = prmt(va[i], vb[i], 0x5410);
                Vn[(2*d2+1)*VSW + vkp] = prmt(va[i], vb[i], 0x7632);
            }
        }

        // ---- online softmax
        const bool diag = (tile >= 2*bm);
        const int colb = tile*64;
#pragma unroll
        for (int mf = 0; mf < 2; mf++) {
            const int r0 = rb + mf*16 + grp;
            const int r1 = r0 + 8;
            float mt0 = -1e30f, mt1 = -1e30f;
#pragma unroll
            for (int nf = 0; nf < 8; nf++) {
                const int c0i = colb + nf*8 + tig*2;
                if (diag) {
                    if (c0i     > r0) sacc[mf][nf][0] = -1e30f;
                    if (c0i + 1 > r0) sacc[mf][nf][1] = -1e30f;
                    if (c0i     > r1) sacc[mf][nf][2] = -1e30f;
                    if (c0i + 1 > r1) sacc[mf][nf][3] = -1e30f;
                }
                mt0 = fmaxf(mt0, fmaxf(sacc[mf][nf][0], sacc[mf][nf][1]));
                mt1 = fmaxf(mt1, fmaxf(sacc[mf][nf][2], sacc[mf][nf][3]));
            }
            mt0 = fmaxf(mt0, __shfl_xor_sync(0xffffffffu, mt0, 1));
            mt0 = fmaxf(mt0, __shfl_xor_sync(0xffffffffu, mt0, 2));
            mt1 = fmaxf(mt1, __shfl_xor_sync(0xffffffffu, mt1, 1));
            mt1 = fmaxf(mt1, __shfl_xor_sync(0xffffffffu, mt1, 2));

            const float mn0 = fmaxf(m[mf*2  ], mt0);
            const float mn1 = fmaxf(m[mf*2+1], mt1);
            const float cr0 = __expf(m[mf*2  ] - mn0);
            const float cr1 = __expf(m[mf*2+1] - mn1);
            float ps0 = 0.f, ps1 = 0.f;

            unsigned* P0 = &Psw[(w*32 + mf*16 + grp)*PSW + tig];
            unsigned* P1 = P0 + 8*PSW;
#pragma unroll
            for (int nf = 0; nf < 8; nf++) {
                float p00 = __expf(sacc[mf][nf][0] - mn0);
                float p01 = __expf(sacc[mf][nf][1] - mn0);
                float p10 = __expf(sacc[mf][nf][2] - mn1);
                float p11 = __expf(sacc[mf][nf][3] - mn1);
                ps0 += p00 + p01;
                ps1 += p10 + p11;
                P0[nf*4] = pack_h2(p00, p01);
                P1[nf*4] = pack_h2(p10, p11);
            }
            ps0 += __shfl_xor_sync(0xffffffffu, ps0, 1);
            ps0 += __shfl_xor_sync(0xffffffffu, ps0, 2);
            ps1 += __shfl_xor_sync(0xffffffffu, ps1, 1);
            ps1 += __shfl_xor_sync(0xffffffffu, ps1, 2);
            l[mf*2  ] = l[mf*2  ]*cr0 + ps0;  m[mf*2  ] = mn0;
            l[mf*2+1] = l[mf*2+1]*cr1 + ps1;  m[mf*2+1] = mn1;
#pragma unroll
            for (int nf = 0; nf < 8; nf++) {
                oacc[mf][nf][0] *= cr0; oacc[mf][nf][1] *= cr0;
                oacc[mf][nf][2] *= cr1; oacc[mf][nf][3] *= cr1;
            }
        }
        __syncwarp();

        // ---- O += P V
#pragma unroll
        for (int kb = 0; kb < 4; kb++) {
            unsigned a[2][4];
#pragma unroll
            for (int mf = 0; mf < 2; mf++) {
                const int pr = w*32 + mf*16 + grp;
                a[mf][0] = Psw[(pr    )*PSW + kb*8 + tig];
                a[mf][1] = Psw[(pr + 8)*PSW + kb*8 + tig];
                a[mf][2] = Psw[(pr    )*PSW + kb*8 + tig + 4];
                a[mf][3] = Psw[(pr + 8)*PSW + kb*8 + tig + 4];
            }
#pragma unroll
            for (int nf = 0; nf < 8; nf++) {
                unsigned b0 = Vtw[(nf*8+grp)*VSW + kb*8 + tig];
                unsigned b1 = Vtw[(nf*8+grp)*VSW + kb*8 + tig + 4];
#pragma unroll
                for (int mf = 0; mf < 2; mf++) {
                    float* c0 = &oacc[mf][nf][0];
                    asm volatile(
                        "mma.sync.aligned.m16n8k16.row.col.f32.f16.f16.f32 "
                        "{%0,%1,%2,%3}, {%4,%5,%6,%7}, {%8,%9}, {%0,%1,%2,%3};"
                        : "+f"(c0[0]), "+f"(c0[1]), "+f"(c0[2]), "+f"(c0[3])
                        : "r"(a[mf][0]), "r"(a[mf][1]), "r"(a[mf][2]), "r"(a[mf][3]),
                          "r"(b0), "r"(b1));
                }
            }
        }
    }

    // ---- epilogue: O / l as half2
#pragma unroll
    for (int mf = 0; mf < 2; mf++) {
        const float inv0 = 1.f / l[mf*2];
        const float inv1 = 1.f / l[mf*2+1];
        unsigned* o0 = O + (((size_t)(b*S_ + rb + mf*16 + grp    )*NH + h) << 5) + tig;
        unsigned* o1 = O + (((size_t)(b*S_ + rb + mf*16 + grp + 8)*NH + h) << 5) + tig;
#pragma unroll
        for (int nf = 0; nf < 8; nf++) {
            o0[nf*4] = pack_h2(oacc[mf][nf][0]*inv0, oacc[mf][nf][1]*inv0);
            o1[nf*4] = pack_h2(oacc[mf][nf][2]*inv1, oacc[mf][nf][3]*inv1);
        }
    }
}

// ---------------------------------------------------------------------------
extern "C" void kernel_launch(void* const* d_in, const int* in_sizes, int n_in,
                              void* d_out, int out_size)
{
    const float* x    = (const float*)d_in[0];
    const float* cosT = (const float*)d_in[1];
    const float* sinT = (const float*)d_in[2];
    const float* wq   = (const float*)d_in[3];
    const float* wk   = (const float*)d_in[4];
    const float* wv   = (const float*)d_in[5];
    const float* wo   = (const float*)d_in[6];
    float* out = (float*)d_out;

    unsigned *Q, *K, *V, *Aat, *X, *Wq, *Wk, *Wv, *Wo;
    cudaGetSymbolAddress((void**)&Q,   g_Q);
    cudaGetSymbolAddress((void**)&K,   g_K);
    cudaGetSymbolAddress((void**)&V,   g_V);
    cudaGetSymbolAddress((void**)&Aat, g_A);
    cudaGetSymbolAddress((void**)&X,   g_X);
    cudaGetSymbolAddress((void**)&Wq,  g_Wq);
    cudaGetSymbolAddress((void**)&Wk,  g_Wk);
    cudaGetSymbolAddress((void**)&Wv,  g_Wv);
    cudaGetSymbolAddress((void**)&Wo,  g_Wo);

    static bool attr_set = false;
    if (!attr_set) {
        cudaFuncSetAttribute(hgemm, cudaFuncAttributeMaxDynamicSharedMemorySize, GEMM_SMEM);
        cudaFuncSetAttribute(flash_attn_fp16, cudaFuncAttributeMaxDynamicSharedMemorySize, FA_SMEM);
        attr_set = true;
    }

    // One-shot fp16 conversion of x + weights
    conv_fp16<<<CONV_BLOCKS, 256>>>(x, wq, wk, wv, wo, X, Wq, Wk, Wv, Wo);

    // Q projection: rope + half out + 1/8 scale (mode 7)
    hgemm<<<dim3(HID/128, MROWS/128), 256, GEMM_SMEM>>>(
        X, Wq, Q, HID/128, 7, nullptr, nullptr, 0,
        MROWS, HID, HID, cosT, sinT);

    // K (rope+half, mode 3) + V (half, mode 2) merged
    hgemm<<<dim3(2*(NKV*HD)/128, MROWS/128), 256, GEMM_SMEM>>>(
        X, Wk, K, (NKV*HD)/128, 3, Wv, V, 2,
        MROWS, NKV*HD, HID, cosT, sinT);

    // fp16 flash attention (double-buffered, pipelined loads, fixed K loader)
    flash_attn_fp16<<<dim3(NH, S_/128, B_), 128, FA_SMEM>>>(Q, K, V, Aat);

    // Output projection: fp32 out (mode 0)
    hgemm<<<dim3(HID/128, MROWS/128), 256, GEMM_SMEM>>>(
        Aat, Wo, out, HID/128, 0, nullptr, nullptr, 0,
        MROWS, HID, HID, cosT, sinT);
}